// round 7
// baseline (speedup 1.0000x reference)
#include <cuda_runtime.h>
#include <cuda_bf16.h>
#include <math.h>
#include <float.h>
#include <stdint.h>

#define SEQ 1024
#define DMODEL 4096
#define NH 32
#define HD 128
#define HB 102
#define RB 102

// ======================= static device scratch =======================
__device__ __align__(256) float g_Q[SEQ * DMODEL];
__device__ __align__(256) float g_K[SEQ * DMODEL];
__device__ __align__(256) float g_V[SEQ * DMODEL];
__device__ __align__(256) float g_P[(size_t)NH * SEQ * SEQ];
__device__ unsigned g_M[NH * SEQ * (SEQ / 32)];
__device__ __align__(256) __nv_bfloat16 g_Xhi[SEQ * DMODEL], g_Xlo[SEQ * DMODEL];
__device__ __align__(256) __nv_bfloat16 g_Whi[4][DMODEL * DMODEL];
__device__ __align__(256) __nv_bfloat16 g_Wlo[4][DMODEL * DMODEL];
__device__ __align__(256) __nv_bfloat16 g_Qhi[SEQ * DMODEL], g_Qlo[SEQ * DMODEL];
__device__ __align__(256) __nv_bfloat16 g_Khi[SEQ * DMODEL], g_Klo[SEQ * DMODEL];
__device__ __align__(256) __nv_bfloat16 g_AOhi[SEQ * DMODEL], g_AOlo[SEQ * DMODEL];

// ======================= helpers =======================
__device__ __forceinline__ uint32_t smem_u32(const void* p) {
    uint32_t a;
    asm("{ .reg .u64 t; cvta.to.shared.u64 t, %1; cvt.u32.u64 %0, t; }" : "=r"(a) : "l"(p));
    return a;
}
__device__ __forceinline__ void cp16(uint32_t dst, const void* src) {
    asm volatile("cp.async.cg.shared.global [%0], [%1], 16;" :: "r"(dst), "l"(src));
}
__device__ __forceinline__ void cp_commit() { asm volatile("cp.async.commit_group;" ::: "memory"); }
__device__ __forceinline__ void cp_wait0() { asm volatile("cp.async.wait_group 0;" ::: "memory"); }
__device__ __forceinline__ void cp_wait1() { asm volatile("cp.async.wait_group 1;" ::: "memory"); }
__device__ __forceinline__ void cp_wait2() { asm volatile("cp.async.wait_group 2;" ::: "memory"); }

__device__ __forceinline__ void ldsm4(uint32_t* r, uint32_t addr) {
    asm volatile("ldmatrix.sync.aligned.m8n8.x4.shared.b16 {%0,%1,%2,%3}, [%4];"
        : "=r"(r[0]), "=r"(r[1]), "=r"(r[2]), "=r"(r[3]) : "r"(addr));
}
__device__ __forceinline__ void mma_bf16(float* c, const uint32_t* a, uint32_t b0, uint32_t b1) {
    asm volatile("mma.sync.aligned.m16n8k16.row.col.f32.bf16.bf16.f32 "
        "{%0,%1,%2,%3}, {%4,%5,%6,%7}, {%8,%9}, {%0,%1,%2,%3};"
        : "+f"(c[0]), "+f"(c[1]), "+f"(c[2]), "+f"(c[3])
        : "r"(a[0]), "r"(a[1]), "r"(a[2]), "r"(a[3]), "r"(b0), "r"(b1));
}

// ======================= split-bf16 HMMA GEMM core =======================
// C[128 x 128] = (Ahi+Alo)[128 x K] * (Bhi+Blo)[128 x K]^T   (lo*lo dropped)
// BK = 32, 3-stage cp.async pipeline, XOR-swizzled smem (64B rows, 4 granules).
// 256 threads = 8 warps: warp grid 4(M) x 2(N), warp tile 32 x 64.
// 96KB total smem -> 2 CTAs/SM.
#define SLAB 8192                      /* 128 rows x 64B */
#define STAGE (4 * SLAB)               /* Ahi|Alo|Bhi|Blo = 32768 */
#define MM_SMEM (3 * STAGE)            /* 98304 */

__device__ __forceinline__ void ld_stage(
    uint32_t st, const __nv_bfloat16* Ahi, const __nv_bfloat16* Alo,
    const __nv_bfloat16* Bhi, const __nv_bfloat16* Blo,
    int lda, int ldb, int k0, int tid)
{
#pragma unroll
    for (int it = 0; it < 2; it++) {          // 512 granules per matrix
        int idx = it * 256 + tid;
        int row = idx >> 2, g = idx & 3;
        uint32_t off = row * 64 + ((g ^ ((row >> 1) & 3)) << 4);
        size_t sa = (size_t)row * lda + k0 + g * 8;
        size_t sbv = (size_t)row * ldb + k0 + g * 8;
        cp16(st + off, Ahi + sa);
        cp16(st + SLAB + off, Alo + sa);
        cp16(st + 2 * SLAB + off, Bhi + sbv);
        cp16(st + 3 * SLAB + off, Blo + sbv);
    }
}

__device__ __forceinline__ void mm_hmma(
    const __nv_bfloat16* __restrict__ Ahi, const __nv_bfloat16* __restrict__ Alo, int lda,
    const __nv_bfloat16* __restrict__ Bhi, const __nv_bfloat16* __restrict__ Blo, int ldb,
    float* __restrict__ C, int ldc, int nk, float scale)
{
    extern __shared__ char smem[];
    const uint32_t sb = smem_u32(smem);
    const int tid = threadIdx.x, lane = tid & 31, wid = tid >> 5;
    const int wm = wid & 3, wn = wid >> 2;

    float c[2][8][4];
#pragma unroll
    for (int i = 0; i < 2; i++)
#pragma unroll
        for (int j = 0; j < 8; j++)
#pragma unroll
            for (int q = 0; q < 4; q++) c[i][j][q] = 0.f;

    ld_stage(sb, Ahi, Alo, Bhi, Blo, lda, ldb, 0, tid); cp_commit();
    if (nk > 1) { ld_stage(sb + STAGE, Ahi, Alo, Bhi, Blo, lda, ldb, 32, tid); cp_commit(); }

    int buf = 0;
    for (int ck = 0; ck < nk; ck++) {
        if (ck + 2 < nk) {
            int nb = buf + 2; if (nb >= 3) nb -= 3;
            ld_stage(sb + nb * STAGE, Ahi, Alo, Bhi, Blo, lda, ldb, (ck + 2) * 32, tid);
            cp_commit();
        }
        if (ck + 2 < nk) cp_wait2();
        else if (ck + 1 < nk) cp_wait1();
        else cp_wait0();
        __syncthreads();
        const uint32_t st = sb + buf * STAGE;
#pragma unroll
        for (int k16 = 0; k16 < 2; k16++) {
            uint32_t ah[2][4], al[2][4];
#pragma unroll
            for (int i = 0; i < 2; i++) {
                int arow = wm * 32 + i * 16 + (lane & 15);
                uint32_t ad = st + (uint32_t)(arow * 64)
                            + (uint32_t)(((2 * k16 + (lane >> 4)) ^ ((arow >> 1) & 3)) << 4);
                ldsm4(ah[i], ad);
                ldsm4(al[i], ad + SLAB);
            }
#pragma unroll
            for (int j4 = 0; j4 < 4; j4++) {
                int brow = wn * 64 + j4 * 16 + ((lane >> 4) << 3) + (lane & 7);
                uint32_t bd = st + 2 * SLAB + (uint32_t)(brow * 64)
                            + (uint32_t)(((2 * k16 + ((lane >> 3) & 1)) ^ ((brow >> 1) & 3)) << 4);
                uint32_t bh[4], bl[4];
                ldsm4(bh, bd);
                ldsm4(bl, bd + SLAB);
#pragma unroll
                for (int i = 0; i < 2; i++) {
                    mma_bf16(c[i][2 * j4],     ah[i], bh[0], bh[1]);
                    mma_bf16(c[i][2 * j4],     ah[i], bl[0], bl[1]);
                    mma_bf16(c[i][2 * j4],     al[i], bh[0], bh[1]);
                    mma_bf16(c[i][2 * j4 + 1], ah[i], bh[2], bh[3]);
                    mma_bf16(c[i][2 * j4 + 1], ah[i], bl[2], bl[3]);
                    mma_bf16(c[i][2 * j4 + 1], al[i], bh[2], bh[3]);
                }
            }
        }
        __syncthreads();
        if (++buf == 3) buf = 0;
    }

    const int r0 = wm * 32 + (lane >> 2);
    const int c0 = wn * 64 + (lane & 3) * 2;
#pragma unroll
    for (int i = 0; i < 2; i++)
#pragma unroll
        for (int j = 0; j < 8; j++) {
            float2 v0 = { c[i][j][0] * scale, c[i][j][1] * scale };
            float2 v1 = { c[i][j][2] * scale, c[i][j][3] * scale };
            *(float2*)&C[(size_t)(r0 + i * 16) * ldc + c0 + j * 8] = v0;
            *(float2*)&C[(size_t)(r0 + i * 16 + 8) * ldc + c0 + j * 8] = v1;
        }
}

// ======================= fused conversion fp32 -> bf16 hi/lo =======================
#define X4 (SEQ * DMODEL / 4)
#define W4 (DMODEL * DMODEL / 4)
__global__ __launch_bounds__(256) void cvt_all_kernel(
    const float* __restrict__ X, const float* __restrict__ Wq,
    const float* __restrict__ Wk, const float* __restrict__ Wv,
    const float* __restrict__ Wo)
{
    long long i = (long long)blockIdx.x * 256 + threadIdx.x;
    const float* src;
    __nv_bfloat16 *hi, *lo;
    long long r;
    if (i < X4)                    { src = X;  hi = g_Xhi;    lo = g_Xlo;    r = i; }
    else if ((r = i - X4) < W4)    { src = Wq; hi = g_Whi[0]; lo = g_Wlo[0]; }
    else if ((r -= W4) < W4)       { src = Wk; hi = g_Whi[1]; lo = g_Wlo[1]; }
    else if ((r -= W4) < W4)       { src = Wv; hi = g_Whi[2]; lo = g_Wlo[2]; }
    else if ((r -= W4) < W4)       { src = Wo; hi = g_Whi[3]; lo = g_Wlo[3]; }
    else return;
    float4 v = ((const float4*)src)[r];
    __nv_bfloat16 h0 = __float2bfloat16(v.x), h1 = __float2bfloat16(v.y);
    __nv_bfloat16 h2 = __float2bfloat16(v.z), h3 = __float2bfloat16(v.w);
    __nv_bfloat162 H01; H01.x = h0; H01.y = h1;
    __nv_bfloat162 H23; H23.x = h2; H23.y = h3;
    __nv_bfloat162 L01, L23;
    L01.x = __float2bfloat16(v.x - __bfloat162float(h0));
    L01.y = __float2bfloat16(v.y - __bfloat162float(h1));
    L23.x = __float2bfloat16(v.z - __bfloat162float(h2));
    L23.y = __float2bfloat16(v.w - __bfloat162float(h3));
    *(__nv_bfloat162*)(hi + 4 * (size_t)r)     = H01;
    *(__nv_bfloat162*)(hi + 4 * (size_t)r + 2) = H23;
    *(__nv_bfloat162*)(lo + 4 * (size_t)r)     = L01;
    *(__nv_bfloat162*)(lo + 4 * (size_t)r + 2) = L23;
}

// ======================= GEMM wrappers =======================
__global__ __launch_bounds__(256, 2) void mm_qkv_kernel()
{
    const int z = blockIdx.z;
    const int m0 = blockIdx.y * 128, n0 = blockIdx.x * 128;
    float* O = (z == 0) ? g_Q : (z == 1) ? g_K : g_V;
    mm_hmma(g_Xhi + (size_t)m0 * DMODEL, g_Xlo + (size_t)m0 * DMODEL, DMODEL,
            g_Whi[z] + (size_t)n0 * DMODEL, g_Wlo[z] + (size_t)n0 * DMODEL, DMODEL,
            O + (size_t)m0 * DMODEL + n0, DMODEL, DMODEL / 32, 1.0f);
}

__global__ __launch_bounds__(256, 2) void mm_o_kernel(float* __restrict__ out)
{
    const int m0 = blockIdx.y * 128, n0 = blockIdx.x * 128;
    mm_hmma(g_AOhi + (size_t)m0 * DMODEL, g_AOlo + (size_t)m0 * DMODEL, DMODEL,
            g_Whi[3] + (size_t)n0 * DMODEL, g_Wlo[3] + (size_t)n0 * DMODEL, DMODEL,
            out + (size_t)m0 * DMODEL + n0, DMODEL, DMODEL / 32, 1.0f);
}

__global__ __launch_bounds__(256, 2) void mm_qk_kernel()
{
    const int h = blockIdx.z;
    const int m0 = blockIdx.y * 128, n0 = blockIdx.x * 128;
    if (n0 > m0 + 127) return;   // tile entirely above diagonal: never read
    mm_hmma(g_Qhi + (size_t)m0 * DMODEL + h * HD, g_Qlo + (size_t)m0 * DMODEL + h * HD, DMODEL,
            g_Khi + (size_t)n0 * DMODEL + h * HD, g_Klo + (size_t)n0 * DMODEL + h * HD, DMODEL,
            g_P + (size_t)h * SEQ * SEQ + (size_t)m0 * SEQ + n0, SEQ,
            HD / 32, 0.08838834764831845f);
}

// ======================= RoPE: fp32 Q/K -> roped bf16 hi/lo =======================
__global__ void rope_kernel()
{
    int idx = blockIdx.x * blockDim.x + threadIdx.x;
    const float* src = blockIdx.y ? g_K : g_Q;
    __nv_bfloat16* hi = blockIdx.y ? g_Khi : g_Qhi;
    __nv_bfloat16* lo = blockIdx.y ? g_Klo : g_Qlo;
    int p = idx & 63;
    int h = (idx >> 6) & 31;
    int s = idx >> 11;
    float inv = 1.0f / powf(10000.0f, (float)(2 * p) * (1.0f / 128.0f));
    float ang = (float)s * inv;
    float sn, c;
    sincosf(ang, &sn, &c);
    size_t b = (size_t)s * DMODEL + h * HD + p;
    float q0 = src[b], q1 = src[b + 64];
    float r0 = q0 * c - q1 * sn;
    float r1 = q1 * c + q0 * sn;
    __nv_bfloat16 h0 = __float2bfloat16(r0);
    __nv_bfloat16 h1 = __float2bfloat16(r1);
    hi[b] = h0;      lo[b]      = __float2bfloat16(r0 - __bfloat162float(h0));
    hi[b + 64] = h1; lo[b + 64] = __float2bfloat16(r1 - __bfloat162float(h1));
}

// ======================= softmax (probs P0, zero above diagonal) =======================
__global__ __launch_bounds__(256) void softmax_kernel()
{
    const int i = blockIdx.x, h = blockIdx.y;
    float* row = g_P + (size_t)h * SEQ * SEQ + (size_t)i * SEQ;
    const int n = i + 1;
    const int tid = threadIdx.x;
    const int lane = tid & 31, wid = tid >> 5;
    __shared__ float red[16];

    float m = -FLT_MAX;
    for (int j = tid; j < n; j += 256) m = fmaxf(m, row[j]);
#pragma unroll
    for (int o = 16; o; o >>= 1) m = fmaxf(m, __shfl_xor_sync(0xffffffffu, m, o));
    if (lane == 0) red[wid] = m;
    __syncthreads();
    m = red[0];
#pragma unroll
    for (int w = 1; w < 8; w++) m = fmaxf(m, red[w]);

    float s = 0.f;
    for (int j = tid; j < n; j += 256) s += expf(row[j] - m);
#pragma unroll
    for (int o = 16; o; o >>= 1) s += __shfl_xor_sync(0xffffffffu, s, o);
    if (lane == 0) red[8 + wid] = s;
    __syncthreads();
    float tot = 0.f;
#pragma unroll
    for (int w = 0; w < 8; w++) tot += red[8 + w];
    const float invs = 1.0f / tot;

    for (int j = tid; j < SEQ; j += 256)
        row[j] = (j < n) ? expf(row[j] - m) * invs : 0.f;
}

// ======================= H2O sequential scan =======================
__global__ __launch_bounds__(128) void scan_kernel()
{
    const int h = blockIdx.x;
    const int tid = threadIdx.x;
    const int lane = tid & 31, wid = tid >> 5;
    __shared__ float acc[SEQ];
    __shared__ float rowbuf[2][SEQ];
    __shared__ int   lst[128];
    __shared__ float skey[128];
    __shared__ unsigned mw[32];
    const float* P = g_P + (size_t)h * SEQ * SEQ;
    unsigned* MB = g_M + h * SEQ * (SEQ / 32);

    for (int j = tid; j < SEQ; j += 128) acc[j] = 0.f;
    __syncthreads();
    if (tid < HB) {
        float s = 0.f;
        for (int i = 0; i < HB; i++) s += P[(size_t)i * SEQ + tid];
        acc[tid] = s;
        lst[tid] = tid;
    }
    {
        uint32_t dst = smem_u32(&rowbuf[HB & 1][0]);
        const float* src = P + (size_t)HB * SEQ;
        for (int g = tid; g < SEQ / 4; g += 128) cp16(dst + g * 16, src + g * 4);
        cp_commit();
    }
    cp_wait0();
    __syncthreads();

    int cnt = HB;
    for (int t = HB; t < SEQ; t++) {
        if (t + 1 < SEQ) {
            uint32_t dst = smem_u32(&rowbuf[(t + 1) & 1][0]);
            const float* src = P + (size_t)(t + 1) * SEQ;
            for (int g = tid; g < SEQ / 4; g += 128) cp16(dst + g * 16, src + g * 4);
            cp_commit();
        }
        if (wid == 0) {
            const float* Prow = rowbuf[t & 1];
            for (int p = lane; p < cnt; p += 32) skey[p] = acc[lst[p]];
            __syncwarp();

            const int r = cnt - (HB - 1);
            for (int rep = 0; rep < r; rep++) {
                float bv = FLT_MAX; int bidx = -1; int bpos = 0;
                for (int p = lane; p < cnt; p += 32) {
                    float v = skey[p]; int ix = lst[p];
                    if (v < bv || (v == bv && ix > bidx)) { bv = v; bidx = ix; bpos = p; }
                }
#pragma unroll
                for (int o = 16; o; o >>= 1) {
                    float ov = __shfl_down_sync(0xffffffffu, bv, o);
                    int   oi = __shfl_down_sync(0xffffffffu, bidx, o);
                    int   op = __shfl_down_sync(0xffffffffu, bpos, o);
                    if (ov < bv || (ov == bv && oi > bidx)) { bv = ov; bidx = oi; bpos = op; }
                }
                bidx = __shfl_sync(0xffffffffu, bidx, 0);
                bpos = __shfl_sync(0xffffffffu, bpos, 0);
                if (bidx >= 4) {
                    if (lane == 0) {
                        acc[bidx] = 0.f;
                        lst[bpos]  = lst[cnt - 1];
                        skey[bpos] = skey[cnt - 1];
                    }
                    cnt--;
                } else {
                    if (lane == 0) skey[bpos] = FLT_MAX;
                }
                __syncwarp();
            }
            if (lane == 0) lst[cnt] = t;
            cnt++;
            mw[lane] = 0u;
            __syncwarp();
            for (int p = lane; p < cnt; p += 32) {
                int ix = lst[p];
                acc[ix] += Prow[ix];
                atomicOr(&mw[ix >> 5], 1u << (ix & 31));
            }
            __syncwarp();
            MB[t * 32 + lane] = mw[lane];
        }
        cp_wait0();
        __syncthreads();
    }
}

// ======================= masked renorm softmax + P@V (writes AO hi/lo) =======================
__global__ __launch_bounds__(128) void pv_kernel()
{
    const int h = blockIdx.y;
    const int tid = threadIdx.x;
    const int lane = tid & 31, wid = tid >> 5;
    __shared__ float pv[224];
    __shared__ int   pj[224];
    __shared__ int   wbase[4];
    __shared__ float wsum[4];
    __shared__ int   s_cnt;
    __shared__ float s_sum;

    for (int u8 = 0; u8 < 8; u8++) {
        const int s = blockIdx.x * 8 + u8;
        const float* Prow = g_P + (size_t)h * SEQ * SEQ + (size_t)s * SEQ;
        const unsigned* mb = g_M + (h * SEQ + s) * (SEQ / 32);

        float pr[8]; bool al[8];
        int c = 0; float lsum = 0.f;
        const int j0 = tid * 8;
#pragma unroll
        for (int u = 0; u < 8; u++) {
            const int j = j0 + u;
            bool a;
            if (s < HB) a = (j <= s);
            else        a = (j <= s) && ((j + RB >= s) || ((mb[j >> 5] >> (j & 31)) & 1u));
            float val = a ? Prow[j] : 0.f;
            al[u] = a; pr[u] = val;
            if (a) { c++; lsum += val; }
        }
        int inc = c;
#pragma unroll
        for (int o = 1; o < 32; o <<= 1) {
            int v = __shfl_up_sync(0xffffffffu, inc, o);
            if (lane >= o) inc += v;
        }
        float ws = lsum;
#pragma unroll
        for (int o = 16; o; o >>= 1) ws += __shfl_xor_sync(0xffffffffu, ws, o);
        if (lane == 31) wbase[wid] = inc;
        if (lane == 0)  wsum[wid] = ws;
        __syncthreads();
        if (tid == 0) {
            int tot = 0;
#pragma unroll
            for (int w = 0; w < 4; w++) { int b = wbase[w]; wbase[w] = tot; tot += b; }
            s_cnt = tot;
            s_sum = wsum[0] + wsum[1] + wsum[2] + wsum[3];
        }
        __syncthreads();
        int k = wbase[wid] + inc - c;
#pragma unroll
        for (int u = 0; u < 8; u++)
            if (al[u]) { pv[k] = pr[u]; pj[k] = j0 + u; k++; }
        __syncthreads();

        const int cnt = s_cnt;
        const float inv = 1.0f / s_sum;
        const float* Vh = g_V + h * HD + tid;
        float acc = 0.f;
        int m2 = 0;
        for (; m2 + 4 <= cnt; m2 += 4) {
            acc += pv[m2 + 0] * Vh[(size_t)pj[m2 + 0] * DMODEL];
            acc += pv[m2 + 1] * Vh[(size_t)pj[m2 + 1] * DMODEL];
            acc += pv[m2 + 2] * Vh[(size_t)pj[m2 + 2] * DMODEL];
            acc += pv[m2 + 3] * Vh[(size_t)pj[m2 + 3] * DMODEL];
        }
        for (; m2 < cnt; m2++) acc += pv[m2] * Vh[(size_t)pj[m2] * DMODEL];

        float v = acc * inv;
        __nv_bfloat16 hv = __float2bfloat16(v);
        size_t oi = (size_t)s * DMODEL + h * HD + tid;
        g_AOhi[oi] = hv;
        g_AOlo[oi] = __float2bfloat16(v - __bfloat162float(hv));
        __syncthreads();
    }
}

// ======================= launch =======================
extern "C" void kernel_launch(void* const* d_in, const int* in_sizes, int n_in,
                              void* d_out, int out_size)
{
    const float* X  = (const float*)d_in[0];
    const float* Wq = (const float*)d_in[2];
    const float* Wk = (const float*)d_in[3];
    const float* Wv = (const float*)d_in[4];
    const float* Wo = (const float*)d_in[5];
    float* out = (float*)d_out;

    cudaFuncSetAttribute(mm_qkv_kernel, cudaFuncAttributeMaxDynamicSharedMemorySize, MM_SMEM);
    cudaFuncSetAttribute(mm_qk_kernel,  cudaFuncAttributeMaxDynamicSharedMemorySize, MM_SMEM);
    cudaFuncSetAttribute(mm_o_kernel,   cudaFuncAttributeMaxDynamicSharedMemorySize, MM_SMEM);

    cvt_all_kernel<<<(X4 + 4 * W4 + 255) / 256, 256>>>(X, Wq, Wk, Wv, Wo);
    mm_qkv_kernel<<<dim3(DMODEL / 128, SEQ / 128, 3), 256, MM_SMEM>>>();
    rope_kernel<<<dim3((SEQ * NH * 64) / 256, 2), 256>>>();
    mm_qk_kernel<<<dim3(SEQ / 128, SEQ / 128, NH), 256, MM_SMEM>>>();
    softmax_kernel<<<dim3(SEQ, NH), 256>>>();
    scan_kernel<<<NH, 128>>>();
    pv_kernel<<<dim3(SEQ / 8, NH), 128>>>();
    mm_o_kernel<<<dim3(DMODEL / 128, SEQ / 128), 256, MM_SMEM>>>(out);
}

// round 8
// speedup vs baseline: 1.0502x; 1.0502x over previous
#include <cuda_runtime.h>
#include <cuda_bf16.h>
#include <math.h>
#include <float.h>
#include <stdint.h>

#define SEQ 1024
#define DMODEL 4096
#define NH 32
#define HD 128
#define HB 102
#define RB 102

// ======================= static device scratch =======================
__device__ __align__(256) float g_Q[SEQ * DMODEL];
__device__ __align__(256) float g_K[SEQ * DMODEL];
__device__ __align__(256) float g_V[SEQ * DMODEL];
__device__ __align__(256) float g_P[(size_t)NH * SEQ * SEQ];
__device__ unsigned g_M[NH * SEQ * (SEQ / 32)];
__device__ __align__(256) __nv_bfloat16 g_Xhi[SEQ * DMODEL], g_Xlo[SEQ * DMODEL];
__device__ __align__(256) __nv_bfloat16 g_Whi[4][DMODEL * DMODEL];
__device__ __align__(256) __nv_bfloat16 g_Wlo[4][DMODEL * DMODEL];
__device__ __align__(256) __nv_bfloat16 g_Qhi[SEQ * DMODEL], g_Qlo[SEQ * DMODEL];
__device__ __align__(256) __nv_bfloat16 g_Khi[SEQ * DMODEL], g_Klo[SEQ * DMODEL];
__device__ __align__(256) __nv_bfloat16 g_AOhi[SEQ * DMODEL], g_AOlo[SEQ * DMODEL];

// ======================= helpers =======================
__device__ __forceinline__ uint32_t smem_u32(const void* p) {
    uint32_t a;
    asm("{ .reg .u64 t; cvta.to.shared.u64 t, %1; cvt.u32.u64 %0, t; }" : "=r"(a) : "l"(p));
    return a;
}
__device__ __forceinline__ void cp16(uint32_t dst, const void* src) {
    asm volatile("cp.async.cg.shared.global [%0], [%1], 16;" :: "r"(dst), "l"(src));
}
__device__ __forceinline__ void cp_commit() { asm volatile("cp.async.commit_group;" ::: "memory"); }
__device__ __forceinline__ void cp_wait1() { asm volatile("cp.async.wait_group 1;" ::: "memory"); }
__device__ __forceinline__ void cp_wait0() { asm volatile("cp.async.wait_group 0;" ::: "memory"); }

__device__ __forceinline__ void ldsm4(uint32_t* r, uint32_t addr) {
    asm volatile("ldmatrix.sync.aligned.m8n8.x4.shared.b16 {%0,%1,%2,%3}, [%4];"
        : "=r"(r[0]), "=r"(r[1]), "=r"(r[2]), "=r"(r[3]) : "r"(addr));
}
__device__ __forceinline__ void mma_bf16(float* c, const uint32_t* a, uint32_t b0, uint32_t b1) {
    asm volatile("mma.sync.aligned.m16n8k16.row.col.f32.bf16.bf16.f32 "
        "{%0,%1,%2,%3}, {%4,%5,%6,%7}, {%8,%9}, {%0,%1,%2,%3};"
        : "+f"(c[0]), "+f"(c[1]), "+f"(c[2]), "+f"(c[3])
        : "r"(a[0]), "r"(a[1]), "r"(a[2]), "r"(a[3]), "r"(b0), "r"(b1));
}

// ======================= split-bf16 HMMA GEMM core =======================
// C[128 x 64] = (Ahi+Alo)[128 x K] * (Bhi+Blo)[64 x K]^T   (lo*lo dropped)
// BK = 64, double-buffered cp.async, XOR-swizzled smem (128B rows).
// 256 threads = 8 warps: warp grid 4(M) x 2(N), warp tile 32 x 32.
// 96KB total smem -> 2 CTAs/SM.
// Schedule: all LDSMs hoisted per k16, MMAs grouped by split term so
// consecutive MMAs never share an accumulator (no RAW chain).
#define A_SLAB 16384
#define B_SLAB 8192
#define STAGE (2 * A_SLAB + 2 * B_SLAB)
#define MM_SMEM (2 * STAGE)

__device__ __forceinline__ void ld_stage(
    uint32_t st, const __nv_bfloat16* Ahi, const __nv_bfloat16* Alo,
    const __nv_bfloat16* Bhi, const __nv_bfloat16* Blo,
    int lda, int ldb, int k0, int tid)
{
#pragma unroll
    for (int it = 0; it < 4; it++) {
        int idx = it * 256 + tid;
        int row = idx >> 3, g = idx & 7;
        uint32_t off = row * 128 + ((g ^ (row & 7)) << 4);
        size_t s = (size_t)row * lda + k0 + g * 8;
        cp16(st + off, Ahi + s);
        cp16(st + A_SLAB + off, Alo + s);
    }
#pragma unroll
    for (int it = 0; it < 2; it++) {
        int idx = it * 256 + tid;
        int row = idx >> 3, g = idx & 7;
        uint32_t off = row * 128 + ((g ^ (row & 7)) << 4);
        size_t s = (size_t)row * ldb + k0 + g * 8;
        cp16(st + 2 * A_SLAB + off, Bhi + s);
        cp16(st + 2 * A_SLAB + B_SLAB + off, Blo + s);
    }
}

__device__ __forceinline__ void mm_hmma(
    const __nv_bfloat16* __restrict__ Ahi, const __nv_bfloat16* __restrict__ Alo, int lda,
    const __nv_bfloat16* __restrict__ Bhi, const __nv_bfloat16* __restrict__ Blo, int ldb,
    float* __restrict__ C, int ldc, int nk, float scale)
{
    extern __shared__ char smem[];
    const uint32_t sb = smem_u32(smem);
    const int tid = threadIdx.x, lane = tid & 31, wid = tid >> 5;
    const int wm = wid & 3, wn = wid >> 2;

    float c[2][4][4];
#pragma unroll
    for (int i = 0; i < 2; i++)
#pragma unroll
        for (int j = 0; j < 4; j++)
#pragma unroll
            for (int q = 0; q < 4; q++) c[i][j][q] = 0.f;

    ld_stage(sb, Ahi, Alo, Bhi, Blo, lda, ldb, 0, tid); cp_commit();
    ld_stage(sb + STAGE, Ahi, Alo, Bhi, Blo, lda, ldb, 64, tid); cp_commit();

    const int axor = lane & 7;
    for (int ck = 0; ck < nk; ck++) {
        if (ck == nk - 1) cp_wait0(); else cp_wait1();
        __syncthreads();
        const uint32_t st = sb + (ck & 1) * STAGE;
#pragma unroll
        for (int k16 = 0; k16 < 4; k16++) {
            // ---- load ALL fragments for this k16 (8 back-to-back LDSMs) ----
            uint32_t ah[2][4], al[2][4], bh[2][4], bl[2][4];
#pragma unroll
            for (int i = 0; i < 2; i++) {
                int arow = wm * 32 + i * 16 + (lane & 15);
                uint32_t ad = st + (uint32_t)(arow * 128)
                            + (uint32_t)(((2 * k16 + (lane >> 4)) ^ axor) << 4);
                ldsm4(ah[i], ad);
                ldsm4(al[i], ad + A_SLAB);
            }
#pragma unroll
            for (int j4 = 0; j4 < 2; j4++) {
                int brow = wn * 32 + j4 * 16 + ((lane >> 4) << 3) + (lane & 7);
                uint32_t bd = st + 2 * A_SLAB + (uint32_t)(brow * 128)
                            + (uint32_t)(((2 * k16 + ((lane >> 3) & 1)) ^ axor) << 4);
                ldsm4(bh[j4], bd);
                ldsm4(bl[j4], bd + B_SLAB);
            }
            // ---- MMAs grouped by split term: no consecutive same-accumulator ----
#pragma unroll
            for (int i = 0; i < 2; i++)
#pragma unroll
                for (int j4 = 0; j4 < 2; j4++) {
                    mma_bf16(c[i][2 * j4],     ah[i], bh[j4][0], bh[j4][1]);
                    mma_bf16(c[i][2 * j4 + 1], ah[i], bh[j4][2], bh[j4][3]);
                }
#pragma unroll
            for (int i = 0; i < 2; i++)
#pragma unroll
                for (int j4 = 0; j4 < 2; j4++) {
                    mma_bf16(c[i][2 * j4],     ah[i], bl[j4][0], bl[j4][1]);
                    mma_bf16(c[i][2 * j4 + 1], ah[i], bl[j4][2], bl[j4][3]);
                }
#pragma unroll
            for (int i = 0; i < 2; i++)
#pragma unroll
                for (int j4 = 0; j4 < 2; j4++) {
                    mma_bf16(c[i][2 * j4],     al[i], bh[j4][0], bh[j4][1]);
                    mma_bf16(c[i][2 * j4 + 1], al[i], bh[j4][2], bh[j4][3]);
                }
        }
        __syncthreads();
        if (ck + 2 < nk) {
            ld_stage(st, Ahi, Alo, Bhi, Blo, lda, ldb, (ck + 2) * 64, tid);
            cp_commit();
        }
    }

    const int r0 = wm * 32 + (lane >> 2);
    const int c0 = wn * 32 + (lane & 3) * 2;
#pragma unroll
    for (int i = 0; i < 2; i++)
#pragma unroll
        for (int j = 0; j < 4; j++) {
            float2 v0 = { c[i][j][0] * scale, c[i][j][1] * scale };
            float2 v1 = { c[i][j][2] * scale, c[i][j][3] * scale };
            *(float2*)&C[(size_t)(r0 + i * 16) * ldc + c0 + j * 8] = v0;
            *(float2*)&C[(size_t)(r0 + i * 16 + 8) * ldc + c0 + j * 8] = v1;
        }
}

// ======================= fused conversion fp32 -> bf16 hi/lo =======================
#define X4 (SEQ * DMODEL / 4)
#define W4 (DMODEL * DMODEL / 4)
__global__ __launch_bounds__(256) void cvt_all_kernel(
    const float* __restrict__ X, const float* __restrict__ Wq,
    const float* __restrict__ Wk, const float* __restrict__ Wv,
    const float* __restrict__ Wo)
{
    long long i = (long long)blockIdx.x * 256 + threadIdx.x;
    const float* src;
    __nv_bfloat16 *hi, *lo;
    long long r;
    if (i < X4)                    { src = X;  hi = g_Xhi;    lo = g_Xlo;    r = i; }
    else if ((r = i - X4) < W4)    { src = Wq; hi = g_Whi[0]; lo = g_Wlo[0]; }
    else if ((r -= W4) < W4)       { src = Wk; hi = g_Whi[1]; lo = g_Wlo[1]; }
    else if ((r -= W4) < W4)       { src = Wv; hi = g_Whi[2]; lo = g_Wlo[2]; }
    else if ((r -= W4) < W4)       { src = Wo; hi = g_Whi[3]; lo = g_Wlo[3]; }
    else return;
    float4 v = ((const float4*)src)[r];
    __nv_bfloat16 h0 = __float2bfloat16(v.x), h1 = __float2bfloat16(v.y);
    __nv_bfloat16 h2 = __float2bfloat16(v.z), h3 = __float2bfloat16(v.w);
    __nv_bfloat162 H01; H01.x = h0; H01.y = h1;
    __nv_bfloat162 H23; H23.x = h2; H23.y = h3;
    __nv_bfloat162 L01, L23;
    L01.x = __float2bfloat16(v.x - __bfloat162float(h0));
    L01.y = __float2bfloat16(v.y - __bfloat162float(h1));
    L23.x = __float2bfloat16(v.z - __bfloat162float(h2));
    L23.y = __float2bfloat16(v.w - __bfloat162float(h3));
    *(__nv_bfloat162*)(hi + 4 * (size_t)r)     = H01;
    *(__nv_bfloat162*)(hi + 4 * (size_t)r + 2) = H23;
    *(__nv_bfloat162*)(lo + 4 * (size_t)r)     = L01;
    *(__nv_bfloat162*)(lo + 4 * (size_t)r + 2) = L23;
}

// ======================= GEMM wrappers =======================
__global__ __launch_bounds__(256, 2) void mm_qkv_kernel()
{
    const int z = blockIdx.z;
    const int m0 = blockIdx.y * 128, n0 = blockIdx.x * 64;
    float* O = (z == 0) ? g_Q : (z == 1) ? g_K : g_V;
    mm_hmma(g_Xhi + (size_t)m0 * DMODEL, g_Xlo + (size_t)m0 * DMODEL, DMODEL,
            g_Whi[z] + (size_t)n0 * DMODEL, g_Wlo[z] + (size_t)n0 * DMODEL, DMODEL,
            O + (size_t)m0 * DMODEL + n0, DMODEL, DMODEL / 64, 1.0f);
}

__global__ __launch_bounds__(256, 2) void mm_o_kernel(float* __restrict__ out)
{
    const int m0 = blockIdx.y * 128, n0 = blockIdx.x * 64;
    mm_hmma(g_AOhi + (size_t)m0 * DMODEL, g_AOlo + (size_t)m0 * DMODEL, DMODEL,
            g_Whi[3] + (size_t)n0 * DMODEL, g_Wlo[3] + (size_t)n0 * DMODEL, DMODEL,
            out + (size_t)m0 * DMODEL + n0, DMODEL, DMODEL / 64, 1.0f);
}

__global__ __launch_bounds__(256, 2) void mm_qk_kernel()
{
    const int h = blockIdx.z;
    const int m0 = blockIdx.y * 128, n0 = blockIdx.x * 64;
    if (n0 > m0 + 127) return;
    mm_hmma(g_Qhi + (size_t)m0 * DMODEL + h * HD, g_Qlo + (size_t)m0 * DMODEL + h * HD, DMODEL,
            g_Khi + (size_t)n0 * DMODEL + h * HD, g_Klo + (size_t)n0 * DMODEL + h * HD, DMODEL,
            g_P + (size_t)h * SEQ * SEQ + (size_t)m0 * SEQ + n0, SEQ,
            HD / 64, 0.08838834764831845f);
}

// ======================= RoPE: fp32 Q/K -> roped bf16 hi/lo =======================
__global__ void rope_kernel()
{
    int idx = blockIdx.x * blockDim.x + threadIdx.x;
    const float* src = blockIdx.y ? g_K : g_Q;
    __nv_bfloat16* hi = blockIdx.y ? g_Khi : g_Qhi;
    __nv_bfloat16* lo = blockIdx.y ? g_Klo : g_Qlo;
    int p = idx & 63;
    int h = (idx >> 6) & 31;
    int s = idx >> 11;
    float inv = 1.0f / powf(10000.0f, (float)(2 * p) * (1.0f / 128.0f));
    float ang = (float)s * inv;
    float sn, c;
    sincosf(ang, &sn, &c);
    size_t b = (size_t)s * DMODEL + h * HD + p;
    float q0 = src[b], q1 = src[b + 64];
    float r0 = q0 * c - q1 * sn;
    float r1 = q1 * c + q0 * sn;
    __nv_bfloat16 h0 = __float2bfloat16(r0);
    __nv_bfloat16 h1 = __float2bfloat16(r1);
    hi[b] = h0;      lo[b]      = __float2bfloat16(r0 - __bfloat162float(h0));
    hi[b + 64] = h1; lo[b + 64] = __float2bfloat16(r1 - __bfloat162float(h1));
}

// ======================= softmax (probs P0, zero above diagonal) =======================
__global__ __launch_bounds__(256) void softmax_kernel()
{
    const int i = blockIdx.x, h = blockIdx.y;
    float* row = g_P + (size_t)h * SEQ * SEQ + (size_t)i * SEQ;
    const int n = i + 1;
    const int tid = threadIdx.x;
    const int lane = tid & 31, wid = tid >> 5;
    __shared__ float red[16];

    float m = -FLT_MAX;
    for (int j = tid; j < n; j += 256) m = fmaxf(m, row[j]);
#pragma unroll
    for (int o = 16; o; o >>= 1) m = fmaxf(m, __shfl_xor_sync(0xffffffffu, m, o));
    if (lane == 0) red[wid] = m;
    __syncthreads();
    m = red[0];
#pragma unroll
    for (int w = 1; w < 8; w++) m = fmaxf(m, red[w]);

    float s = 0.f;
    for (int j = tid; j < n; j += 256) s += expf(row[j] - m);
#pragma unroll
    for (int o = 16; o; o >>= 1) s += __shfl_xor_sync(0xffffffffu, s, o);
    if (lane == 0) red[8 + wid] = s;
    __syncthreads();
    float tot = 0.f;
#pragma unroll
    for (int w = 0; w < 8; w++) tot += red[8 + w];
    const float invs = 1.0f / tot;

    for (int j = tid; j < SEQ; j += 256)
        row[j] = (j < n) ? expf(row[j] - m) * invs : 0.f;
}

// ======================= H2O sequential scan =======================
__global__ __launch_bounds__(128) void scan_kernel()
{
    const int h = blockIdx.x;
    const int tid = threadIdx.x;
    const int lane = tid & 31, wid = tid >> 5;
    __shared__ float acc[SEQ];
    __shared__ float rowbuf[2][SEQ];
    __shared__ int   lst[128];
    __shared__ float skey[128];
    __shared__ unsigned mw[32];
    const float* P = g_P + (size_t)h * SEQ * SEQ;
    unsigned* MB = g_M + h * SEQ * (SEQ / 32);

    for (int j = tid; j < SEQ; j += 128) acc[j] = 0.f;
    __syncthreads();
    if (tid < HB) {
        float s = 0.f;
        for (int i = 0; i < HB; i++) s += P[(size_t)i * SEQ + tid];
        acc[tid] = s;
        lst[tid] = tid;
    }
    {
        uint32_t dst = smem_u32(&rowbuf[HB & 1][0]);
        const float* src = P + (size_t)HB * SEQ;
        for (int g = tid; g < SEQ / 4; g += 128) cp16(dst + g * 16, src + g * 4);
        cp_commit();
    }
    cp_wait0();
    __syncthreads();

    int cnt = HB;
    for (int t = HB; t < SEQ; t++) {
        if (t + 1 < SEQ) {
            uint32_t dst = smem_u32(&rowbuf[(t + 1) & 1][0]);
            const float* src = P + (size_t)(t + 1) * SEQ;
            for (int g = tid; g < SEQ / 4; g += 128) cp16(dst + g * 16, src + g * 4);
            cp_commit();
        }
        if (wid == 0) {
            const float* Prow = rowbuf[t & 1];
            for (int p = lane; p < cnt; p += 32) skey[p] = acc[lst[p]];
            __syncwarp();

            const int r = cnt - (HB - 1);
            for (int rep = 0; rep < r; rep++) {
                float bv = FLT_MAX; int bidx = -1; int bpos = 0;
                for (int p = lane; p < cnt; p += 32) {
                    float v = skey[p]; int ix = lst[p];
                    if (v < bv || (v == bv && ix > bidx)) { bv = v; bidx = ix; bpos = p; }
                }
#pragma unroll
                for (int o = 16; o; o >>= 1) {
                    float ov = __shfl_down_sync(0xffffffffu, bv, o);
                    int   oi = __shfl_down_sync(0xffffffffu, bidx, o);
                    int   op = __shfl_down_sync(0xffffffffu, bpos, o);
                    if (ov < bv || (ov == bv && oi > bidx)) { bv = ov; bidx = oi; bpos = op; }
                }
                bidx = __shfl_sync(0xffffffffu, bidx, 0);
                bpos = __shfl_sync(0xffffffffu, bpos, 0);
                if (bidx >= 4) {
                    if (lane == 0) {
                        acc[bidx] = 0.f;
                        lst[bpos]  = lst[cnt - 1];
                        skey[bpos] = skey[cnt - 1];
                    }
                    cnt--;
                } else {
                    if (lane == 0) skey[bpos] = FLT_MAX;
                }
                __syncwarp();
            }
            if (lane == 0) lst[cnt] = t;
            cnt++;
            mw[lane] = 0u;
            __syncwarp();
            for (int p = lane; p < cnt; p += 32) {
                int ix = lst[p];
                acc[ix] += Prow[ix];
                atomicOr(&mw[ix >> 5], 1u << (ix & 31));
            }
            __syncwarp();
            MB[t * 32 + lane] = mw[lane];
        }
        cp_wait0();
        __syncthreads();
    }
}

// ======================= masked renorm softmax + P@V (writes AO hi/lo) =======================
__global__ __launch_bounds__(128) void pv_kernel()
{
    const int h = blockIdx.y;
    const int tid = threadIdx.x;
    const int lane = tid & 31, wid = tid >> 5;
    __shared__ float pv[224];
    __shared__ int   pj[224];
    __shared__ int   wbase[4];
    __shared__ float wsum[4];
    __shared__ int   s_cnt;
    __shared__ float s_sum;

    for (int u8 = 0; u8 < 8; u8++) {
        const int s = blockIdx.x * 8 + u8;
        const float* Prow = g_P + (size_t)h * SEQ * SEQ + (size_t)s * SEQ;
        const unsigned* mb = g_M + (h * SEQ + s) * (SEQ / 32);

        float pr[8]; bool al[8];
        int c = 0; float lsum = 0.f;
        const int j0 = tid * 8;
#pragma unroll
        for (int u = 0; u < 8; u++) {
            const int j = j0 + u;
            bool a;
            if (s < HB) a = (j <= s);
            else        a = (j <= s) && ((j + RB >= s) || ((mb[j >> 5] >> (j & 31)) & 1u));
            float val = a ? Prow[j] : 0.f;
            al[u] = a; pr[u] = val;
            if (a) { c++; lsum += val; }
        }
        int inc = c;
#pragma unroll
        for (int o = 1; o < 32; o <<= 1) {
            int v = __shfl_up_sync(0xffffffffu, inc, o);
            if (lane >= o) inc += v;
        }
        float ws = lsum;
#pragma unroll
        for (int o = 16; o; o >>= 1) ws += __shfl_xor_sync(0xffffffffu, ws, o);
        if (lane == 31) wbase[wid] = inc;
        if (lane == 0)  wsum[wid] = ws;
        __syncthreads();
        if (tid == 0) {
            int tot = 0;
#pragma unroll
            for (int w = 0; w < 4; w++) { int b = wbase[w]; wbase[w] = tot; tot += b; }
            s_cnt = tot;
            s_sum = wsum[0] + wsum[1] + wsum[2] + wsum[3];
        }
        __syncthreads();
        int k = wbase[wid] + inc - c;
#pragma unroll
        for (int u = 0; u < 8; u++)
            if (al[u]) { pv[k] = pr[u]; pj[k] = j0 + u; k++; }
        __syncthreads();

        const int cnt = s_cnt;
        const float inv = 1.0f / s_sum;
        const float* Vh = g_V + h * HD + tid;
        float acc = 0.f;
        int m2 = 0;
        for (; m2 + 4 <= cnt; m2 += 4) {
            acc += pv[m2 + 0] * Vh[(size_t)pj[m2 + 0] * DMODEL];
            acc += pv[m2 + 1] * Vh[(size_t)pj[m2 + 1] * DMODEL];
            acc += pv[m2 + 2] * Vh[(size_t)pj[m2 + 2] * DMODEL];
            acc += pv[m2 + 3] * Vh[(size_t)pj[m2 + 3] * DMODEL];
        }
        for (; m2 < cnt; m2++) acc += pv[m2] * Vh[(size_t)pj[m2] * DMODEL];

        float v = acc * inv;
        __nv_bfloat16 hv = __float2bfloat16(v);
        size_t oi = (size_t)s * DMODEL + h * HD + tid;
        g_AOhi[oi] = hv;
        g_AOlo[oi] = __float2bfloat16(v - __bfloat162float(hv));
        __syncthreads();
    }
}

// ======================= launch =======================
extern "C" void kernel_launch(void* const* d_in, const int* in_sizes, int n_in,
                              void* d_out, int out_size)
{
    const float* X  = (const float*)d_in[0];
    const float* Wq = (const float*)d_in[2];
    const float* Wk = (const float*)d_in[3];
    const float* Wv = (const float*)d_in[4];
    const float* Wo = (const float*)d_in[5];
    float* out = (float*)d_out;

    cudaFuncSetAttribute(mm_qkv_kernel, cudaFuncAttributeMaxDynamicSharedMemorySize, MM_SMEM);
    cudaFuncSetAttribute(mm_qk_kernel,  cudaFuncAttributeMaxDynamicSharedMemorySize, MM_SMEM);
    cudaFuncSetAttribute(mm_o_kernel,   cudaFuncAttributeMaxDynamicSharedMemorySize, MM_SMEM);

    cvt_all_kernel<<<(X4 + 4 * W4 + 255) / 256, 256>>>(X, Wq, Wk, Wv, Wo);
    mm_qkv_kernel<<<dim3(DMODEL / 64, SEQ / 128, 3), 256, MM_SMEM>>>();
    rope_kernel<<<dim3((SEQ * NH * 64) / 256, 2), 256>>>();
    mm_qk_kernel<<<dim3(SEQ / 64, SEQ / 128, NH), 256, MM_SMEM>>>();
    softmax_kernel<<<dim3(SEQ, NH), 256>>>();
    scan_kernel<<<NH, 128>>>();
    pv_kernel<<<dim3(SEQ / 8, NH), 128>>>();
    mm_o_kernel<<<dim3(DMODEL / 64, SEQ / 128), 256, MM_SMEM>>>(out);
}

// round 9
// speedup vs baseline: 1.1000x; 1.0475x over previous
#include <cuda_runtime.h>
#include <cuda_fp16.h>
#include <math.h>
#include <float.h>
#include <stdint.h>

#define SEQ 1024
#define DMODEL 4096
#define NH 32
#define HD 128
#define HB 102
#define RB 102

// ======================= static device scratch =======================
__device__ __align__(256) float g_Q[SEQ * DMODEL];
__device__ __align__(256) float g_K[SEQ * DMODEL];
__device__ __align__(256) float g_V[SEQ * DMODEL];
__device__ __align__(256) float g_P[(size_t)NH * SEQ * SEQ];
__device__ unsigned g_M[NH * SEQ * (SEQ / 32)];
__device__ __align__(256) __half g_Xhi[SEQ * DMODEL], g_Xlo[SEQ * DMODEL];
__device__ __align__(256) __half g_Whi[4][DMODEL * DMODEL];
__device__ __align__(256) __half g_Wlo[4][DMODEL * DMODEL];
__device__ __align__(256) __half g_Qhi[SEQ * DMODEL], g_Qlo[SEQ * DMODEL];
__device__ __align__(256) __half g_Khi[SEQ * DMODEL], g_Klo[SEQ * DMODEL];
__device__ __align__(256) __half g_AOhi[SEQ * DMODEL], g_AOlo[SEQ * DMODEL];

// ======================= helpers =======================
__device__ __forceinline__ uint32_t smem_u32(const void* p) {
    uint32_t a;
    asm("{ .reg .u64 t; cvta.to.shared.u64 t, %1; cvt.u32.u64 %0, t; }" : "=r"(a) : "l"(p));
    return a;
}
__device__ __forceinline__ void cp16(uint32_t dst, const void* src) {
    asm volatile("cp.async.cg.shared.global [%0], [%1], 16;" :: "r"(dst), "l"(src));
}
__device__ __forceinline__ void cp_commit() { asm volatile("cp.async.commit_group;" ::: "memory"); }
__device__ __forceinline__ void cp_wait1() { asm volatile("cp.async.wait_group 1;" ::: "memory"); }
__device__ __forceinline__ void cp_wait0() { asm volatile("cp.async.wait_group 0;" ::: "memory"); }

__device__ __forceinline__ void ldsm4(uint32_t* r, uint32_t addr) {
    asm volatile("ldmatrix.sync.aligned.m8n8.x4.shared.b16 {%0,%1,%2,%3}, [%4];"
        : "=r"(r[0]), "=r"(r[1]), "=r"(r[2]), "=r"(r[3]) : "r"(addr));
}
__device__ __forceinline__ void mma_fp16(float* c, const uint32_t* a, uint32_t b0, uint32_t b1) {
    asm volatile("mma.sync.aligned.m16n8k16.row.col.f32.f16.f16.f32 "
        "{%0,%1,%2,%3}, {%4,%5,%6,%7}, {%8,%9}, {%0,%1,%2,%3};"
        : "+f"(c[0]), "+f"(c[1]), "+f"(c[2]), "+f"(c[3])
        : "r"(a[0]), "r"(a[1]), "r"(a[2]), "r"(a[3]), "r"(b0), "r"(b1));
}

// ======================= split-fp16 HMMA GEMM core =======================
// terms==3: C = Ahi*Bhi^T + Alo*Bhi^T + Ahi*Blo^T   (Q/K/logits paths)
// terms==2: C = Ahi*Bhi^T + Alo*Bhi^T               (V / O linear paths;
//            B residual dropped, B-lo never loaded)
// BK = 64, double-buffered cp.async, XOR-swizzled smem (128B rows).
// 256 threads = 8 warps: warp grid 4(M) x 2(N), warp tile 32 x 32.
// 96KB total smem -> 2 CTAs/SM.
#define A_SLAB 16384
#define B_SLAB 8192
#define STAGE (2 * A_SLAB + 2 * B_SLAB)
#define MM_SMEM (2 * STAGE)

__device__ __forceinline__ void ld_stage(
    uint32_t st, const __half* Ahi, const __half* Alo,
    const __half* Bhi, const __half* Blo,
    int lda, int ldb, int k0, int tid, int terms)
{
#pragma unroll
    for (int it = 0; it < 4; it++) {
        int idx = it * 256 + tid;
        int row = idx >> 3, g = idx & 7;
        uint32_t off = row * 128 + ((g ^ (row & 7)) << 4);
        size_t s = (size_t)row * lda + k0 + g * 8;
        cp16(st + off, Ahi + s);
        cp16(st + A_SLAB + off, Alo + s);
    }
#pragma unroll
    for (int it = 0; it < 2; it++) {
        int idx = it * 256 + tid;
        int row = idx >> 3, g = idx & 7;
        uint32_t off = row * 128 + ((g ^ (row & 7)) << 4);
        size_t s = (size_t)row * ldb + k0 + g * 8;
        cp16(st + 2 * A_SLAB + off, Bhi + s);
        if (terms == 3)
            cp16(st + 2 * A_SLAB + B_SLAB + off, Blo + s);
    }
}

__device__ __forceinline__ void mm_hmma(
    const __half* __restrict__ Ahi, const __half* __restrict__ Alo, int lda,
    const __half* __restrict__ Bhi, const __half* __restrict__ Blo, int ldb,
    float* __restrict__ C, int ldc, int nk, float scale, int terms)
{
    extern __shared__ char smem[];
    const uint32_t sb = smem_u32(smem);
    const int tid = threadIdx.x, lane = tid & 31, wid = tid >> 5;
    const int wm = wid & 3, wn = wid >> 2;

    float c[2][4][4];
#pragma unroll
    for (int i = 0; i < 2; i++)
#pragma unroll
        for (int j = 0; j < 4; j++)
#pragma unroll
            for (int q = 0; q < 4; q++) c[i][j][q] = 0.f;

    ld_stage(sb, Ahi, Alo, Bhi, Blo, lda, ldb, 0, tid, terms); cp_commit();
    ld_stage(sb + STAGE, Ahi, Alo, Bhi, Blo, lda, ldb, 64, tid, terms); cp_commit();

    const int axor = lane & 7;
    for (int ck = 0; ck < nk; ck++) {
        if (ck == nk - 1) cp_wait0(); else cp_wait1();
        __syncthreads();
        const uint32_t st = sb + (ck & 1) * STAGE;
#pragma unroll
        for (int k16 = 0; k16 < 4; k16++) {
            // ---- hoisted fragment loads ----
            uint32_t ah[2][4], al[2][4], bh[2][4], bl[2][4];
#pragma unroll
            for (int i = 0; i < 2; i++) {
                int arow = wm * 32 + i * 16 + (lane & 15);
                uint32_t ad = st + (uint32_t)(arow * 128)
                            + (uint32_t)(((2 * k16 + (lane >> 4)) ^ axor) << 4);
                ldsm4(ah[i], ad);
                ldsm4(al[i], ad + A_SLAB);
            }
#pragma unroll
            for (int j4 = 0; j4 < 2; j4++) {
                int brow = wn * 32 + j4 * 16 + ((lane >> 4) << 3) + (lane & 7);
                uint32_t bd = st + 2 * A_SLAB + (uint32_t)(brow * 128)
                            + (uint32_t)(((2 * k16 + ((lane >> 3) & 1)) ^ axor) << 4);
                ldsm4(bh[j4], bd);
                if (terms == 3) ldsm4(bl[j4], bd + B_SLAB);
            }
            // ---- term 1: Ahi * Bhi ----
#pragma unroll
            for (int i = 0; i < 2; i++)
#pragma unroll
                for (int j4 = 0; j4 < 2; j4++) {
                    mma_fp16(c[i][2 * j4],     ah[i], bh[j4][0], bh[j4][1]);
                    mma_fp16(c[i][2 * j4 + 1], ah[i], bh[j4][2], bh[j4][3]);
                }
            // ---- term 2: Alo * Bhi ----
#pragma unroll
            for (int i = 0; i < 2; i++)
#pragma unroll
                for (int j4 = 0; j4 < 2; j4++) {
                    mma_fp16(c[i][2 * j4],     al[i], bh[j4][0], bh[j4][1]);
                    mma_fp16(c[i][2 * j4 + 1], al[i], bh[j4][2], bh[j4][3]);
                }
            // ---- term 3: Ahi * Blo (only for precision-critical paths) ----
            if (terms == 3) {
#pragma unroll
                for (int i = 0; i < 2; i++)
#pragma unroll
                    for (int j4 = 0; j4 < 2; j4++) {
                        mma_fp16(c[i][2 * j4],     ah[i], bl[j4][0], bl[j4][1]);
                        mma_fp16(c[i][2 * j4 + 1], ah[i], bl[j4][2], bl[j4][3]);
                    }
            }
        }
        __syncthreads();
        if (ck + 2 < nk) {
            ld_stage(st, Ahi, Alo, Bhi, Blo, lda, ldb, (ck + 2) * 64, tid, terms);
            cp_commit();
        }
    }

    const int r0 = wm * 32 + (lane >> 2);
    const int c0 = wn * 32 + (lane & 3) * 2;
#pragma unroll
    for (int i = 0; i < 2; i++)
#pragma unroll
        for (int j = 0; j < 4; j++) {
            float2 v0 = { c[i][j][0] * scale, c[i][j][1] * scale };
            float2 v1 = { c[i][j][2] * scale, c[i][j][3] * scale };
            *(float2*)&C[(size_t)(r0 + i * 16) * ldc + c0 + j * 8] = v0;
            *(float2*)&C[(size_t)(r0 + i * 16 + 8) * ldc + c0 + j * 8] = v1;
        }
}

// ======================= fused conversion fp32 -> fp16 hi/lo =======================
#define X4 (SEQ * DMODEL / 4)
#define W4 (DMODEL * DMODEL / 4)
__global__ __launch_bounds__(256) void cvt_all_kernel(
    const float* __restrict__ X, const float* __restrict__ Wq,
    const float* __restrict__ Wk, const float* __restrict__ Wv,
    const float* __restrict__ Wo)
{
    long long i = (long long)blockIdx.x * 256 + threadIdx.x;
    const float* src;
    __half *hi, *lo;
    long long r;
    if (i < X4)                    { src = X;  hi = g_Xhi;    lo = g_Xlo;    r = i; }
    else if ((r = i - X4) < W4)    { src = Wq; hi = g_Whi[0]; lo = g_Wlo[0]; }
    else if ((r -= W4) < W4)       { src = Wk; hi = g_Whi[1]; lo = g_Wlo[1]; }
    else if ((r -= W4) < W4)       { src = Wv; hi = g_Whi[2]; lo = g_Wlo[2]; }
    else if ((r -= W4) < W4)       { src = Wo; hi = g_Whi[3]; lo = g_Wlo[3]; }
    else return;
    float4 v = ((const float4*)src)[r];
    __half h0 = __float2half(v.x), h1 = __float2half(v.y);
    __half h2 = __float2half(v.z), h3 = __float2half(v.w);
    __half2 H01; H01.x = h0; H01.y = h1;
    __half2 H23; H23.x = h2; H23.y = h3;
    __half2 L01, L23;
    L01.x = __float2half(v.x - __half2float(h0));
    L01.y = __float2half(v.y - __half2float(h1));
    L23.x = __float2half(v.z - __half2float(h2));
    L23.y = __float2half(v.w - __half2float(h3));
    *(__half2*)(hi + 4 * (size_t)r)     = H01;
    *(__half2*)(hi + 4 * (size_t)r + 2) = H23;
    *(__half2*)(lo + 4 * (size_t)r)     = L01;
    *(__half2*)(lo + 4 * (size_t)r + 2) = L23;
}

// ======================= GEMM wrappers =======================
__global__ __launch_bounds__(256, 2) void mm_qkv_kernel()
{
    const int z = blockIdx.z;
    const int m0 = blockIdx.y * 128, n0 = blockIdx.x * 64;
    float* O = (z == 0) ? g_Q : (z == 1) ? g_K : g_V;
    const int terms = (z == 2) ? 2 : 3;   // V is a linear path: 2-term suffices
    mm_hmma(g_Xhi + (size_t)m0 * DMODEL, g_Xlo + (size_t)m0 * DMODEL, DMODEL,
            g_Whi[z] + (size_t)n0 * DMODEL, g_Wlo[z] + (size_t)n0 * DMODEL, DMODEL,
            O + (size_t)m0 * DMODEL + n0, DMODEL, DMODEL / 64, 1.0f, terms);
}

__global__ __launch_bounds__(256, 2) void mm_o_kernel(float* __restrict__ out)
{
    const int m0 = blockIdx.y * 128, n0 = blockIdx.x * 64;
    mm_hmma(g_AOhi + (size_t)m0 * DMODEL, g_AOlo + (size_t)m0 * DMODEL, DMODEL,
            g_Whi[3] + (size_t)n0 * DMODEL, g_Wlo[3] + (size_t)n0 * DMODEL, DMODEL,
            out + (size_t)m0 * DMODEL + n0, DMODEL, DMODEL / 64, 1.0f, 2);
}

__global__ __launch_bounds__(256, 2) void mm_qk_kernel()
{
    const int h = blockIdx.z;
    const int m0 = blockIdx.y * 128, n0 = blockIdx.x * 64;
    if (n0 > m0 + 127) return;
    mm_hmma(g_Qhi + (size_t)m0 * DMODEL + h * HD, g_Qlo + (size_t)m0 * DMODEL + h * HD, DMODEL,
            g_Khi + (size_t)n0 * DMODEL + h * HD, g_Klo + (size_t)n0 * DMODEL + h * HD, DMODEL,
            g_P + (size_t)h * SEQ * SEQ + (size_t)m0 * SEQ + n0, SEQ,
            HD / 64, 0.08838834764831845f, 3);
}

// ======================= RoPE: fp32 Q/K -> roped fp16 hi/lo =======================
__global__ void rope_kernel()
{
    int idx = blockIdx.x * blockDim.x + threadIdx.x;
    const float* src = blockIdx.y ? g_K : g_Q;
    __half* hi = blockIdx.y ? g_Khi : g_Qhi;
    __half* lo = blockIdx.y ? g_Klo : g_Qlo;
    int p = idx & 63;
    int h = (idx >> 6) & 31;
    int s = idx >> 11;
    float inv = 1.0f / powf(10000.0f, (float)(2 * p) * (1.0f / 128.0f));
    float ang = (float)s * inv;
    float sn, c;
    sincosf(ang, &sn, &c);
    size_t b = (size_t)s * DMODEL + h * HD + p;
    float q0 = src[b], q1 = src[b + 64];
    float r0 = q0 * c - q1 * sn;
    float r1 = q1 * c + q0 * sn;
    __half h0 = __float2half(r0);
    __half h1 = __float2half(r1);
    hi[b] = h0;      lo[b]      = __float2half(r0 - __half2float(h0));
    hi[b + 64] = h1; lo[b + 64] = __float2half(r1 - __half2float(h1));
}

// ======================= softmax (probs P0, zero above diagonal) =======================
__global__ __launch_bounds__(256) void softmax_kernel()
{
    const int i = blockIdx.x, h = blockIdx.y;
    float* row = g_P + (size_t)h * SEQ * SEQ + (size_t)i * SEQ;
    const int n = i + 1;
    const int tid = threadIdx.x;
    const int lane = tid & 31, wid = tid >> 5;
    __shared__ float red[16];

    float m = -FLT_MAX;
    for (int j = tid; j < n; j += 256) m = fmaxf(m, row[j]);
#pragma unroll
    for (int o = 16; o; o >>= 1) m = fmaxf(m, __shfl_xor_sync(0xffffffffu, m, o));
    if (lane == 0) red[wid] = m;
    __syncthreads();
    m = red[0];
#pragma unroll
    for (int w = 1; w < 8; w++) m = fmaxf(m, red[w]);

    float s = 0.f;
    for (int j = tid; j < n; j += 256) s += expf(row[j] - m);
#pragma unroll
    for (int o = 16; o; o >>= 1) s += __shfl_xor_sync(0xffffffffu, s, o);
    if (lane == 0) red[8 + wid] = s;
    __syncthreads();
    float tot = 0.f;
#pragma unroll
    for (int w = 0; w < 8; w++) tot += red[8 + w];
    const float invs = 1.0f / tot;

    for (int j = tid; j < SEQ; j += 256)
        row[j] = (j < n) ? expf(row[j] - m) * invs : 0.f;
}

// ======================= H2O sequential scan =======================
__global__ __launch_bounds__(128) void scan_kernel()
{
    const int h = blockIdx.x;
    const int tid = threadIdx.x;
    const int lane = tid & 31, wid = tid >> 5;
    __shared__ float acc[SEQ];
    __shared__ float rowbuf[2][SEQ];
    __shared__ int   lst[128];
    __shared__ float skey[128];
    __shared__ unsigned mw[32];
    const float* P = g_P + (size_t)h * SEQ * SEQ;
    unsigned* MB = g_M + h * SEQ * (SEQ / 32);

    for (int j = tid; j < SEQ; j += 128) acc[j] = 0.f;
    __syncthreads();
    if (tid < HB) {
        float s = 0.f;
        for (int i = 0; i < HB; i++) s += P[(size_t)i * SEQ + tid];
        acc[tid] = s;
        lst[tid] = tid;
    }
    {
        uint32_t dst = smem_u32(&rowbuf[HB & 1][0]);
        const float* src = P + (size_t)HB * SEQ;
        for (int g = tid; g < SEQ / 4; g += 128) cp16(dst + g * 16, src + g * 4);
        cp_commit();
    }
    cp_wait0();
    __syncthreads();

    int cnt = HB;
    for (int t = HB; t < SEQ; t++) {
        if (t + 1 < SEQ) {
            uint32_t dst = smem_u32(&rowbuf[(t + 1) & 1][0]);
            const float* src = P + (size_t)(t + 1) * SEQ;
            for (int g = tid; g < SEQ / 4; g += 128) cp16(dst + g * 16, src + g * 4);
            cp_commit();
        }
        if (wid == 0) {
            const float* Prow = rowbuf[t & 1];
            for (int p = lane; p < cnt; p += 32) skey[p] = acc[lst[p]];
            __syncwarp();

            const int r = cnt - (HB - 1);
            for (int rep = 0; rep < r; rep++) {
                float bv = FLT_MAX; int bidx = -1; int bpos = 0;
                for (int p = lane; p < cnt; p += 32) {
                    float v = skey[p]; int ix = lst[p];
                    if (v < bv || (v == bv && ix > bidx)) { bv = v; bidx = ix; bpos = p; }
                }
#pragma unroll
                for (int o = 16; o; o >>= 1) {
                    float ov = __shfl_down_sync(0xffffffffu, bv, o);
                    int   oi = __shfl_down_sync(0xffffffffu, bidx, o);
                    int   op = __shfl_down_sync(0xffffffffu, bpos, o);
                    if (ov < bv || (ov == bv && oi > bidx)) { bv = ov; bidx = oi; bpos = op; }
                }
                bidx = __shfl_sync(0xffffffffu, bidx, 0);
                bpos = __shfl_sync(0xffffffffu, bpos, 0);
                if (bidx >= 4) {
                    if (lane == 0) {
                        acc[bidx] = 0.f;
                        lst[bpos]  = lst[cnt - 1];
                        skey[bpos] = skey[cnt - 1];
                    }
                    cnt--;
                } else {
                    if (lane == 0) skey[bpos] = FLT_MAX;
                }
                __syncwarp();
            }
            if (lane == 0) lst[cnt] = t;
            cnt++;
            mw[lane] = 0u;
            __syncwarp();
            for (int p = lane; p < cnt; p += 32) {
                int ix = lst[p];
                acc[ix] += Prow[ix];
                atomicOr(&mw[ix >> 5], 1u << (ix & 31));
            }
            __syncwarp();
            MB[t * 32 + lane] = mw[lane];
        }
        cp_wait0();
        __syncthreads();
    }
}

// ======================= masked renorm softmax + P@V (writes AO hi/lo) =======================
__global__ __launch_bounds__(128) void pv_kernel()
{
    const int h = blockIdx.y;
    const int tid = threadIdx.x;
    const int lane = tid & 31, wid = tid >> 5;
    __shared__ float pv[224];
    __shared__ int   pj[224];
    __shared__ int   wbase[4];
    __shared__ float wsum[4];
    __shared__ int   s_cnt;
    __shared__ float s_sum;

    for (int u8 = 0; u8 < 8; u8++) {
        const int s = blockIdx.x * 8 + u8;
        const float* Prow = g_P + (size_t)h * SEQ * SEQ + (size_t)s * SEQ;
        const unsigned* mb = g_M + (h * SEQ + s) * (SEQ / 32);

        float pr[8]; bool al[8];
        int c = 0; float lsum = 0.f;
        const int j0 = tid * 8;
#pragma unroll
        for (int u = 0; u < 8; u++) {
            const int j = j0 + u;
            bool a;
            if (s < HB) a = (j <= s);
            else        a = (j <= s) && ((j + RB >= s) || ((mb[j >> 5] >> (j & 31)) & 1u));
            float val = a ? Prow[j] : 0.f;
            al[u] = a; pr[u] = val;
            if (a) { c++; lsum += val; }
        }
        int inc = c;
#pragma unroll
        for (int o = 1; o < 32; o <<= 1) {
            int v = __shfl_up_sync(0xffffffffu, inc, o);
            if (lane >= o) inc += v;
        }
        float ws = lsum;
#pragma unroll
        for (int o = 16; o; o >>= 1) ws += __shfl_xor_sync(0xffffffffu, ws, o);
        if (lane == 31) wbase[wid] = inc;
        if (lane == 0)  wsum[wid] = ws;
        __syncthreads();
        if (tid == 0) {
            int tot = 0;
#pragma unroll
            for (int w = 0; w < 4; w++) { int b = wbase[w]; wbase[w] = tot; tot += b; }
            s_cnt = tot;
            s_sum = wsum[0] + wsum[1] + wsum[2] + wsum[3];
        }
        __syncthreads();
        int k = wbase[wid] + inc - c;
#pragma unroll
        for (int u = 0; u < 8; u++)
            if (al[u]) { pv[k] = pr[u]; pj[k] = j0 + u; k++; }
        __syncthreads();

        const int cnt = s_cnt;
        const float inv = 1.0f / s_sum;
        const float* Vh = g_V + h * HD + tid;
        float acc = 0.f;
        int m2 = 0;
        for (; m2 + 4 <= cnt; m2 += 4) {
            acc += pv[m2 + 0] * Vh[(size_t)pj[m2 + 0] * DMODEL];
            acc += pv[m2 + 1] * Vh[(size_t)pj[m2 + 1] * DMODEL];
            acc += pv[m2 + 2] * Vh[(size_t)pj[m2 + 2] * DMODEL];
            acc += pv[m2 + 3] * Vh[(size_t)pj[m2 + 3] * DMODEL];
        }
        for (; m2 < cnt; m2++) acc += pv[m2] * Vh[(size_t)pj[m2] * DMODEL];

        float v = acc * inv;
        __half hv = __float2half(v);
        size_t oi = (size_t)s * DMODEL + h * HD + tid;
        g_AOhi[oi] = hv;
        g_AOlo[oi] = __float2half(v - __half2float(hv));
        __syncthreads();
    }
}

// ======================= launch =======================
extern "C" void kernel_launch(void* const* d_in, const int* in_sizes, int n_in,
                              void* d_out, int out_size)
{
    const float* X  = (const float*)d_in[0];
    const float* Wq = (const float*)d_in[2];
    const float* Wk = (const float*)d_in[3];
    const float* Wv = (const float*)d_in[4];
    const float* Wo = (const float*)d_in[5];
    float* out = (float*)d_out;

    cudaFuncSetAttribute(mm_qkv_kernel, cudaFuncAttributeMaxDynamicSharedMemorySize, MM_SMEM);
    cudaFuncSetAttribute(mm_qk_kernel,  cudaFuncAttributeMaxDynamicSharedMemorySize, MM_SMEM);
    cudaFuncSetAttribute(mm_o_kernel,   cudaFuncAttributeMaxDynamicSharedMemorySize, MM_SMEM);

    cvt_all_kernel<<<(X4 + 4 * W4 + 255) / 256, 256>>>(X, Wq, Wk, Wv, Wo);
    mm_qkv_kernel<<<dim3(DMODEL / 64, SEQ / 128, 3), 256, MM_SMEM>>>();
    rope_kernel<<<dim3((SEQ * NH * 64) / 256, 2), 256>>>();
    mm_qk_kernel<<<dim3(SEQ / 64, SEQ / 128, NH), 256, MM_SMEM>>>();
    softmax_kernel<<<dim3(SEQ, NH), 256>>>();
    scan_kernel<<<NH, 128>>>();
    pv_kernel<<<dim3(SEQ / 8, NH), 128>>>();
    mm_o_kernel<<<dim3(DMODEL / 64, SEQ / 128), 256, MM_SMEM>>>(out);
}

// round 10
// speedup vs baseline: 1.1278x; 1.0252x over previous
#include <cuda_runtime.h>
#include <cuda_fp16.h>
#include <math.h>
#include <float.h>
#include <stdint.h>

#define SEQ 1024
#define DMODEL 4096
#define NH 32
#define HD 128
#define HB 102
#define RB 102

// ======================= static device scratch =======================
__device__ __align__(256) float g_Q[SEQ * DMODEL];
__device__ __align__(256) float g_K[SEQ * DMODEL];
__device__ __align__(256) float g_V[SEQ * DMODEL];
__device__ __align__(256) float g_P[(size_t)NH * SEQ * SEQ];
__device__ unsigned g_M[NH * SEQ * (SEQ / 32)];
__device__ __align__(256) __half g_Xhi[SEQ * DMODEL], g_Xlo[SEQ * DMODEL];
__device__ __align__(256) __half g_Whi[4][DMODEL * DMODEL];
__device__ __align__(256) __half g_Wlo[4][DMODEL * DMODEL];
__device__ __align__(256) __half g_Qhi[SEQ * DMODEL], g_Qlo[SEQ * DMODEL];
__device__ __align__(256) __half g_Khi[SEQ * DMODEL], g_Klo[SEQ * DMODEL];
__device__ __align__(256) __half g_AOhi[SEQ * DMODEL], g_AOlo[SEQ * DMODEL];

// ======================= helpers =======================
__device__ __forceinline__ uint32_t smem_u32(const void* p) {
    uint32_t a;
    asm("{ .reg .u64 t; cvta.to.shared.u64 t, %1; cvt.u32.u64 %0, t; }" : "=r"(a) : "l"(p));
    return a;
}
__device__ __forceinline__ void cp16(uint32_t dst, const void* src) {
    asm volatile("cp.async.cg.shared.global [%0], [%1], 16;" :: "r"(dst), "l"(src));
}
__device__ __forceinline__ void cp_commit() { asm volatile("cp.async.commit_group;" ::: "memory"); }
__device__ __forceinline__ void cp_wait1() { asm volatile("cp.async.wait_group 1;" ::: "memory"); }
__device__ __forceinline__ void cp_wait0() { asm volatile("cp.async.wait_group 0;" ::: "memory"); }

__device__ __forceinline__ void ldsm4(uint32_t* r, uint32_t addr) {
    asm volatile("ldmatrix.sync.aligned.m8n8.x4.shared.b16 {%0,%1,%2,%3}, [%4];"
        : "=r"(r[0]), "=r"(r[1]), "=r"(r[2]), "=r"(r[3]) : "r"(addr));
}
__device__ __forceinline__ void mma_fp16(float* c, const uint32_t* a, uint32_t b0, uint32_t b1) {
    asm volatile("mma.sync.aligned.m16n8k16.row.col.f32.f16.f16.f32 "
        "{%0,%1,%2,%3}, {%4,%5,%6,%7}, {%8,%9}, {%0,%1,%2,%3};"
        : "+f"(c[0]), "+f"(c[1]), "+f"(c[2]), "+f"(c[3])
        : "r"(a[0]), "r"(a[1]), "r"(a[2]), "r"(a[3]), "r"(b0), "r"(b1));
}

// ======================= split-fp16 HMMA GEMM core =======================
// terms==3: C = Ahi*Bhi^T + Alo*Bhi^T + Ahi*Blo^T   (Q/K/logits paths)
// terms==2: C = Ahi*Bhi^T + Alo*Bhi^T               (V / O linear paths)
#define A_SLAB 16384
#define B_SLAB 8192
#define STAGE (2 * A_SLAB + 2 * B_SLAB)
#define MM_SMEM (2 * STAGE)

__device__ __forceinline__ void ld_stage(
    uint32_t st, const __half* Ahi, const __half* Alo,
    const __half* Bhi, const __half* Blo,
    int lda, int ldb, int k0, int tid, int terms)
{
#pragma unroll
    for (int it = 0; it < 4; it++) {
        int idx = it * 256 + tid;
        int row = idx >> 3, g = idx & 7;
        uint32_t off = row * 128 + ((g ^ (row & 7)) << 4);
        size_t s = (size_t)row * lda + k0 + g * 8;
        cp16(st + off, Ahi + s);
        cp16(st + A_SLAB + off, Alo + s);
    }
#pragma unroll
    for (int it = 0; it < 2; it++) {
        int idx = it * 256 + tid;
        int row = idx >> 3, g = idx & 7;
        uint32_t off = row * 128 + ((g ^ (row & 7)) << 4);
        size_t s = (size_t)row * ldb + k0 + g * 8;
        cp16(st + 2 * A_SLAB + off, Bhi + s);
        if (terms == 3)
            cp16(st + 2 * A_SLAB + B_SLAB + off, Blo + s);
    }
}

__device__ __forceinline__ void mm_hmma(
    const __half* __restrict__ Ahi, const __half* __restrict__ Alo, int lda,
    const __half* __restrict__ Bhi, const __half* __restrict__ Blo, int ldb,
    float* __restrict__ C, int ldc, int nk, float scale, int terms)
{
    extern __shared__ char smem[];
    const uint32_t sb = smem_u32(smem);
    const int tid = threadIdx.x, lane = tid & 31, wid = tid >> 5;
    const int wm = wid & 3, wn = wid >> 2;

    float c[2][4][4];
#pragma unroll
    for (int i = 0; i < 2; i++)
#pragma unroll
        for (int j = 0; j < 4; j++)
#pragma unroll
            for (int q = 0; q < 4; q++) c[i][j][q] = 0.f;

    ld_stage(sb, Ahi, Alo, Bhi, Blo, lda, ldb, 0, tid, terms); cp_commit();
    ld_stage(sb + STAGE, Ahi, Alo, Bhi, Blo, lda, ldb, 64, tid, terms); cp_commit();

    const int axor = lane & 7;
    for (int ck = 0; ck < nk; ck++) {
        if (ck == nk - 1) cp_wait0(); else cp_wait1();
        __syncthreads();
        const uint32_t st = sb + (ck & 1) * STAGE;
#pragma unroll
        for (int k16 = 0; k16 < 4; k16++) {
            uint32_t ah[2][4], al[2][4], bh[2][4], bl[2][4];
#pragma unroll
            for (int i = 0; i < 2; i++) {
                int arow = wm * 32 + i * 16 + (lane & 15);
                uint32_t ad = st + (uint32_t)(arow * 128)
                            + (uint32_t)(((2 * k16 + (lane >> 4)) ^ axor) << 4);
                ldsm4(ah[i], ad);
                ldsm4(al[i], ad + A_SLAB);
            }
#pragma unroll
            for (int j4 = 0; j4 < 2; j4++) {
                int brow = wn * 32 + j4 * 16 + ((lane >> 4) << 3) + (lane & 7);
                uint32_t bd = st + 2 * A_SLAB + (uint32_t)(brow * 128)
                            + (uint32_t)(((2 * k16 + ((lane >> 3) & 1)) ^ axor) << 4);
                ldsm4(bh[j4], bd);
                if (terms == 3) ldsm4(bl[j4], bd + B_SLAB);
            }
#pragma unroll
            for (int i = 0; i < 2; i++)
#pragma unroll
                for (int j4 = 0; j4 < 2; j4++) {
                    mma_fp16(c[i][2 * j4],     ah[i], bh[j4][0], bh[j4][1]);
                    mma_fp16(c[i][2 * j4 + 1], ah[i], bh[j4][2], bh[j4][3]);
                }
#pragma unroll
            for (int i = 0; i < 2; i++)
#pragma unroll
                for (int j4 = 0; j4 < 2; j4++) {
                    mma_fp16(c[i][2 * j4],     al[i], bh[j4][0], bh[j4][1]);
                    mma_fp16(c[i][2 * j4 + 1], al[i], bh[j4][2], bh[j4][3]);
                }
            if (terms == 3) {
#pragma unroll
                for (int i = 0; i < 2; i++)
#pragma unroll
                    for (int j4 = 0; j4 < 2; j4++) {
                        mma_fp16(c[i][2 * j4],     ah[i], bl[j4][0], bl[j4][1]);
                        mma_fp16(c[i][2 * j4 + 1], ah[i], bl[j4][2], bl[j4][3]);
                    }
            }
        }
        __syncthreads();
        if (ck + 2 < nk) {
            ld_stage(st, Ahi, Alo, Bhi, Blo, lda, ldb, (ck + 2) * 64, tid, terms);
            cp_commit();
        }
    }

    const int r0 = wm * 32 + (lane >> 2);
    const int c0 = wn * 32 + (lane & 3) * 2;
#pragma unroll
    for (int i = 0; i < 2; i++)
#pragma unroll
        for (int j = 0; j < 4; j++) {
            float2 v0 = { c[i][j][0] * scale, c[i][j][1] * scale };
            float2 v1 = { c[i][j][2] * scale, c[i][j][3] * scale };
            *(float2*)&C[(size_t)(r0 + i * 16) * ldc + c0 + j * 8] = v0;
            *(float2*)&C[(size_t)(r0 + i * 16 + 8) * ldc + c0 + j * 8] = v1;
        }
}

// ======================= conversion fp32 -> fp16 hi/lo =======================
#define X4 (SEQ * DMODEL / 4)
#define W4 (DMODEL * DMODEL / 4)

__device__ __forceinline__ void cvt_one(const float* src, __half* hi, __half* lo, long long r)
{
    float4 v = ((const float4*)src)[r];
    __half h0 = __float2half(v.x), h1 = __float2half(v.y);
    __half h2 = __float2half(v.z), h3 = __float2half(v.w);
    __half2 H01; H01.x = h0; H01.y = h1;
    __half2 H23; H23.x = h2; H23.y = h3;
    __half2 L01, L23;
    L01.x = __float2half(v.x - __half2float(h0));
    L01.y = __float2half(v.y - __half2float(h1));
    L23.x = __float2half(v.z - __half2float(h2));
    L23.y = __float2half(v.w - __half2float(h3));
    *(__half2*)(hi + 4 * (size_t)r)     = H01;
    *(__half2*)(hi + 4 * (size_t)r + 2) = H23;
    *(__half2*)(lo + 4 * (size_t)r)     = L01;
    *(__half2*)(lo + 4 * (size_t)r + 2) = L23;
}

// X, Wq, Wk (main-path inputs)
__global__ __launch_bounds__(256) void cvt_main_kernel(
    const float* __restrict__ X, const float* __restrict__ Wq,
    const float* __restrict__ Wk)
{
    long long i = (long long)blockIdx.x * 256 + threadIdx.x;
    if (i < X4)                        cvt_one(X,  g_Xhi,    g_Xlo,    i);
    else if ((i -= X4) < W4)           cvt_one(Wq, g_Whi[0], g_Wlo[0], i);
    else if ((i -= W4) < W4)           cvt_one(Wk, g_Whi[1], g_Wlo[1], i);
}

// Wv, Wo (deferred-path inputs)
__global__ __launch_bounds__(256) void cvt_aux_kernel(
    const float* __restrict__ Wv, const float* __restrict__ Wo)
{
    long long i = (long long)blockIdx.x * 256 + threadIdx.x;
    if (i < W4)                        cvt_one(Wv, g_Whi[2], g_Wlo[2], i);
    else if ((i -= W4) < W4)           cvt_one(Wo, g_Whi[3], g_Wlo[3], i);
}

// ======================= GEMM wrappers =======================
__global__ __launch_bounds__(256, 2) void mm_qkproj_kernel()
{
    const int z = blockIdx.z;            // 0: Q, 1: K  (3-term, precision-critical)
    const int m0 = blockIdx.y * 128, n0 = blockIdx.x * 64;
    float* O = (z == 0) ? g_Q : g_K;
    mm_hmma(g_Xhi + (size_t)m0 * DMODEL, g_Xlo + (size_t)m0 * DMODEL, DMODEL,
            g_Whi[z] + (size_t)n0 * DMODEL, g_Wlo[z] + (size_t)n0 * DMODEL, DMODEL,
            O + (size_t)m0 * DMODEL + n0, DMODEL, DMODEL / 64, 1.0f, 3);
}

__global__ __launch_bounds__(256, 2) void mm_v_kernel()
{
    const int m0 = blockIdx.y * 128, n0 = blockIdx.x * 64;
    mm_hmma(g_Xhi + (size_t)m0 * DMODEL, g_Xlo + (size_t)m0 * DMODEL, DMODEL,
            g_Whi[2] + (size_t)n0 * DMODEL, g_Wlo[2] + (size_t)n0 * DMODEL, DMODEL,
            g_V + (size_t)m0 * DMODEL + n0, DMODEL, DMODEL / 64, 1.0f, 2);
}

__global__ __launch_bounds__(256, 2) void mm_o_kernel(float* __restrict__ out)
{
    const int m0 = blockIdx.y * 128, n0 = blockIdx.x * 64;
    mm_hmma(g_AOhi + (size_t)m0 * DMODEL, g_AOlo + (size_t)m0 * DMODEL, DMODEL,
            g_Whi[3] + (size_t)n0 * DMODEL, g_Wlo[3] + (size_t)n0 * DMODEL, DMODEL,
            out + (size_t)m0 * DMODEL + n0, DMODEL, DMODEL / 64, 1.0f, 2);
}

__global__ __launch_bounds__(256, 2) void mm_qk_kernel()
{
    const int h = blockIdx.z;
    const int m0 = blockIdx.y * 128, n0 = blockIdx.x * 64;
    if (n0 > m0 + 127) return;
    mm_hmma(g_Qhi + (size_t)m0 * DMODEL + h * HD, g_Qlo + (size_t)m0 * DMODEL + h * HD, DMODEL,
            g_Khi + (size_t)n0 * DMODEL + h * HD, g_Klo + (size_t)n0 * DMODEL + h * HD, DMODEL,
            g_P + (size_t)h * SEQ * SEQ + (size_t)m0 * SEQ + n0, SEQ,
            HD / 64, 0.08838834764831845f, 3);
}

// ======================= RoPE: fp32 Q/K -> roped fp16 hi/lo =======================
__global__ void rope_kernel()
{
    int idx = blockIdx.x * blockDim.x + threadIdx.x;
    const float* src = blockIdx.y ? g_K : g_Q;
    __half* hi = blockIdx.y ? g_Khi : g_Qhi;
    __half* lo = blockIdx.y ? g_Klo : g_Qlo;
    int p = idx & 63;
    int h = (idx >> 6) & 31;
    int s = idx >> 11;
    float inv = 1.0f / powf(10000.0f, (float)(2 * p) * (1.0f / 128.0f));
    float ang = (float)s * inv;
    float sn, c;
    sincosf(ang, &sn, &c);
    size_t b = (size_t)s * DMODEL + h * HD + p;
    float q0 = src[b], q1 = src[b + 64];
    float r0 = q0 * c - q1 * sn;
    float r1 = q1 * c + q0 * sn;
    __half h0 = __float2half(r0);
    __half h1 = __float2half(r1);
    hi[b] = h0;      lo[b]      = __float2half(r0 - __half2float(h0));
    hi[b + 64] = h1; lo[b + 64] = __float2half(r1 - __half2float(h1));
}

// ======================= softmax (probs P0, zero above diagonal) =======================
__global__ __launch_bounds__(256) void softmax_kernel()
{
    const int i = blockIdx.x, h = blockIdx.y;
    float* row = g_P + (size_t)h * SEQ * SEQ + (size_t)i * SEQ;
    const int n = i + 1;
    const int tid = threadIdx.x;
    const int lane = tid & 31, wid = tid >> 5;
    __shared__ float red[16];

    float m = -FLT_MAX;
    for (int j = tid; j < n; j += 256) m = fmaxf(m, row[j]);
#pragma unroll
    for (int o = 16; o; o >>= 1) m = fmaxf(m, __shfl_xor_sync(0xffffffffu, m, o));
    if (lane == 0) red[wid] = m;
    __syncthreads();
    m = red[0];
#pragma unroll
    for (int w = 1; w < 8; w++) m = fmaxf(m, red[w]);

    float s = 0.f;
    for (int j = tid; j < n; j += 256) s += expf(row[j] - m);
#pragma unroll
    for (int o = 16; o; o >>= 1) s += __shfl_xor_sync(0xffffffffu, s, o);
    if (lane == 0) red[8 + wid] = s;
    __syncthreads();
    float tot = 0.f;
#pragma unroll
    for (int w = 0; w < 8; w++) tot += red[8 + w];
    const float invs = 1.0f / tot;

    for (int j = tid; j < SEQ; j += 256)
        row[j] = (j < n) ? expf(row[j] - m) * invs : 0.f;
}

// ======================= H2O sequential scan =======================
__global__ __launch_bounds__(128) void scan_kernel()
{
    const int h = blockIdx.x;
    const int tid = threadIdx.x;
    const int lane = tid & 31, wid = tid >> 5;
    __shared__ float acc[SEQ];
    __shared__ float rowbuf[2][SEQ];
    __shared__ int   lst[128];
    __shared__ float skey[128];
    __shared__ unsigned mw[32];
    const float* P = g_P + (size_t)h * SEQ * SEQ;
    unsigned* MB = g_M + h * SEQ * (SEQ / 32);

    for (int j = tid; j < SEQ; j += 128) acc[j] = 0.f;
    __syncthreads();
    if (tid < HB) {
        float s = 0.f;
        for (int i = 0; i < HB; i++) s += P[(size_t)i * SEQ + tid];
        acc[tid] = s;
        lst[tid] = tid;
    }
    {
        uint32_t dst = smem_u32(&rowbuf[HB & 1][0]);
        const float* src = P + (size_t)HB * SEQ;
        for (int g = tid; g < SEQ / 4; g += 128) cp16(dst + g * 16, src + g * 4);
        cp_commit();
    }
    cp_wait0();
    __syncthreads();

    int cnt = HB;
    for (int t = HB; t < SEQ; t++) {
        if (t + 1 < SEQ) {
            uint32_t dst = smem_u32(&rowbuf[(t + 1) & 1][0]);
            const float* src = P + (size_t)(t + 1) * SEQ;
            for (int g = tid; g < SEQ / 4; g += 128) cp16(dst + g * 16, src + g * 4);
            cp_commit();
        }
        if (wid == 0) {
            const float* Prow = rowbuf[t & 1];
            for (int p = lane; p < cnt; p += 32) skey[p] = acc[lst[p]];
            __syncwarp();

            const int r = cnt - (HB - 1);
            for (int rep = 0; rep < r; rep++) {
                float bv = FLT_MAX; int bidx = -1; int bpos = 0;
                for (int p = lane; p < cnt; p += 32) {
                    float v = skey[p]; int ix = lst[p];
                    if (v < bv || (v == bv && ix > bidx)) { bv = v; bidx = ix; bpos = p; }
                }
#pragma unroll
                for (int o = 16; o; o >>= 1) {
                    float ov = __shfl_down_sync(0xffffffffu, bv, o);
                    int   oi = __shfl_down_sync(0xffffffffu, bidx, o);
                    int   op = __shfl_down_sync(0xffffffffu, bpos, o);
                    if (ov < bv || (ov == bv && oi > bidx)) { bv = ov; bidx = oi; bpos = op; }
                }
                bidx = __shfl_sync(0xffffffffu, bidx, 0);
                bpos = __shfl_sync(0xffffffffu, bpos, 0);
                if (bidx >= 4) {
                    if (lane == 0) {
                        acc[bidx] = 0.f;
                        lst[bpos]  = lst[cnt - 1];
                        skey[bpos] = skey[cnt - 1];
                    }
                    cnt--;
                } else {
                    if (lane == 0) skey[bpos] = FLT_MAX;
                }
                __syncwarp();
            }
            if (lane == 0) lst[cnt] = t;
            cnt++;
            mw[lane] = 0u;
            __syncwarp();
            for (int p = lane; p < cnt; p += 32) {
                int ix = lst[p];
                acc[ix] += Prow[ix];
                atomicOr(&mw[ix >> 5], 1u << (ix & 31));
            }
            __syncwarp();
            MB[t * 32 + lane] = mw[lane];
        }
        cp_wait0();
        __syncthreads();
    }
}

// ======================= masked renorm softmax + P@V (writes AO hi/lo) =======================
__global__ __launch_bounds__(128) void pv_kernel()
{
    const int h = blockIdx.y;
    const int tid = threadIdx.x;
    const int lane = tid & 31, wid = tid >> 5;
    __shared__ float pv[224];
    __shared__ int   pj[224];
    __shared__ int   wbase[4];
    __shared__ float wsum[4];
    __shared__ int   s_cnt;
    __shared__ float s_sum;

    for (int u8 = 0; u8 < 8; u8++) {
        const int s = blockIdx.x * 8 + u8;
        const float* Prow = g_P + (size_t)h * SEQ * SEQ + (size_t)s * SEQ;
        const unsigned* mb = g_M + (h * SEQ + s) * (SEQ / 32);

        float pr[8]; bool al[8];
        int c = 0; float lsum = 0.f;
        const int j0 = tid * 8;
#pragma unroll
        for (int u = 0; u < 8; u++) {
            const int j = j0 + u;
            bool a;
            if (s < HB) a = (j <= s);
            else        a = (j <= s) && ((j + RB >= s) || ((mb[j >> 5] >> (j & 31)) & 1u));
            float val = a ? Prow[j] : 0.f;
            al[u] = a; pr[u] = val;
            if (a) { c++; lsum += val; }
        }
        int inc = c;
#pragma unroll
        for (int o = 1; o < 32; o <<= 1) {
            int v = __shfl_up_sync(0xffffffffu, inc, o);
            if (lane >= o) inc += v;
        }
        float ws = lsum;
#pragma unroll
        for (int o = 16; o; o >>= 1) ws += __shfl_xor_sync(0xffffffffu, ws, o);
        if (lane == 31) wbase[wid] = inc;
        if (lane == 0)  wsum[wid] = ws;
        __syncthreads();
        if (tid == 0) {
            int tot = 0;
#pragma unroll
            for (int w = 0; w < 4; w++) { int b = wbase[w]; wbase[w] = tot; tot += b; }
            s_cnt = tot;
            s_sum = wsum[0] + wsum[1] + wsum[2] + wsum[3];
        }
        __syncthreads();
        int k = wbase[wid] + inc - c;
#pragma unroll
        for (int u = 0; u < 8; u++)
            if (al[u]) { pv[k] = pr[u]; pj[k] = j0 + u; k++; }
        __syncthreads();

        const int cnt = s_cnt;
        const float inv = 1.0f / s_sum;
        const float* Vh = g_V + h * HD + tid;
        float acc = 0.f;
        int m2 = 0;
        for (; m2 + 4 <= cnt; m2 += 4) {
            acc += pv[m2 + 0] * Vh[(size_t)pj[m2 + 0] * DMODEL];
            acc += pv[m2 + 1] * Vh[(size_t)pj[m2 + 1] * DMODEL];
            acc += pv[m2 + 2] * Vh[(size_t)pj[m2 + 2] * DMODEL];
            acc += pv[m2 + 3] * Vh[(size_t)pj[m2 + 3] * DMODEL];
        }
        for (; m2 < cnt; m2++) acc += pv[m2] * Vh[(size_t)pj[m2] * DMODEL];

        float v = acc * inv;
        __half hv = __float2half(v);
        size_t oi = (size_t)s * DMODEL + h * HD + tid;
        g_AOhi[oi] = hv;
        g_AOlo[oi] = __float2half(v - __half2float(hv));
        __syncthreads();
    }
}

// ======================= launch (fork-join streams inside capture) =======================
extern "C" void kernel_launch(void* const* d_in, const int* in_sizes, int n_in,
                              void* d_out, int out_size)
{
    const float* X  = (const float*)d_in[0];
    const float* Wq = (const float*)d_in[2];
    const float* Wk = (const float*)d_in[3];
    const float* Wv = (const float*)d_in[4];
    const float* Wo = (const float*)d_in[5];
    float* out = (float*)d_out;

    // one-time host-side resources (no device memory involved)
    static cudaStream_t s_aux = 0;
    static cudaEvent_t ev_begin = 0, ev_xcvt = 0, ev_vdone = 0;
    if (!s_aux) {
        int lo_p, hi_p;
        cudaDeviceGetStreamPriorityRange(&lo_p, &hi_p);
        cudaStreamCreateWithPriority(&s_aux, cudaStreamNonBlocking, lo_p); // lowest prio
        cudaEventCreateWithFlags(&ev_begin, cudaEventDisableTiming);
        cudaEventCreateWithFlags(&ev_xcvt,  cudaEventDisableTiming);
        cudaEventCreateWithFlags(&ev_vdone, cudaEventDisableTiming);
    }

    cudaFuncSetAttribute(mm_qkproj_kernel, cudaFuncAttributeMaxDynamicSharedMemorySize, MM_SMEM);
    cudaFuncSetAttribute(mm_v_kernel,      cudaFuncAttributeMaxDynamicSharedMemorySize, MM_SMEM);
    cudaFuncSetAttribute(mm_qk_kernel,     cudaFuncAttributeMaxDynamicSharedMemorySize, MM_SMEM);
    cudaFuncSetAttribute(mm_o_kernel,      cudaFuncAttributeMaxDynamicSharedMemorySize, MM_SMEM);

    // fork aux stream into the capture
    cudaEventRecord(ev_begin, 0);
    cudaStreamWaitEvent(s_aux, ev_begin, 0);

    // aux: convert Wv, Wo (independent of main path)
    cvt_aux_kernel<<<(2 * W4 + 255) / 256, 256, 0, s_aux>>>(Wv, Wo);

    // main: convert X, Wq, Wk then run the logits-critical path
    cvt_main_kernel<<<(X4 + 2 * W4 + 255) / 256, 256>>>(X, Wq, Wk);
    cudaEventRecord(ev_xcvt, 0);

    mm_qkproj_kernel<<<dim3(DMODEL / 64, SEQ / 128, 2), 256, MM_SMEM>>>();
    rope_kernel<<<dim3((SEQ * NH * 64) / 256, 2), 256>>>();
    mm_qk_kernel<<<dim3(SEQ / 64, SEQ / 128, NH), 256, MM_SMEM>>>();
    softmax_kernel<<<dim3(SEQ, NH), 256>>>();
    scan_kernel<<<NH, 128>>>();

    // aux: V projection (needs X conversion) — low priority, fills idle SMs
    cudaStreamWaitEvent(s_aux, ev_xcvt, 0);
    mm_v_kernel<<<dim3(DMODEL / 64, SEQ / 128), 256, MM_SMEM, s_aux>>>();
    cudaEventRecord(ev_vdone, s_aux);

    // join: pv needs V + scan masks
    cudaStreamWaitEvent(0, ev_vdone, 0);
    pv_kernel<<<dim3(SEQ / 8, NH), 128>>>();
    mm_o_kernel<<<dim3(DMODEL / 64, SEQ / 128), 256, MM_SMEM>>>(out);
}

// round 11
// speedup vs baseline: 1.1867x; 1.0522x over previous
#include <cuda_runtime.h>
#include <cuda_fp16.h>
#include <math.h>
#include <float.h>
#include <stdint.h>

#define SEQ 1024
#define DMODEL 4096
#define NH 32
#define HD 128
#define HB 102
#define RB 102

// ======================= static device scratch =======================
__device__ __align__(256) float g_Q[SEQ * DMODEL];
__device__ __align__(256) float g_K[SEQ * DMODEL];
__device__ __align__(256) float g_V[SEQ * DMODEL];
__device__ __align__(256) float g_P[(size_t)NH * SEQ * SEQ];
__device__ unsigned g_M[NH * SEQ * (SEQ / 32)];
__device__ __align__(256) __half g_Xhi[SEQ * DMODEL], g_Xlo[SEQ * DMODEL];
__device__ __align__(256) __half g_Whi[4][DMODEL * DMODEL];
__device__ __align__(256) __half g_Wlo_unused[1];   // weight residuals no longer used
__device__ __align__(256) __half g_Qhi[SEQ * DMODEL], g_Qlo[SEQ * DMODEL];
__device__ __align__(256) __half g_Khi[SEQ * DMODEL], g_Klo[SEQ * DMODEL];
__device__ __align__(256) __half g_AOhi[SEQ * DMODEL], g_AOlo[SEQ * DMODEL];

// ======================= helpers =======================
__device__ __forceinline__ uint32_t smem_u32(const void* p) {
    uint32_t a;
    asm("{ .reg .u64 t; cvta.to.shared.u64 t, %1; cvt.u32.u64 %0, t; }" : "=r"(a) : "l"(p));
    return a;
}
__device__ __forceinline__ void cp16(uint32_t dst, const void* src) {
    asm volatile("cp.async.cg.shared.global [%0], [%1], 16;" :: "r"(dst), "l"(src));
}
__device__ __forceinline__ void cp_commit() { asm volatile("cp.async.commit_group;" ::: "memory"); }
__device__ __forceinline__ void cp_wait1() { asm volatile("cp.async.wait_group 1;" ::: "memory"); }
__device__ __forceinline__ void cp_wait0() { asm volatile("cp.async.wait_group 0;" ::: "memory"); }

__device__ __forceinline__ void ldsm4(uint32_t* r, uint32_t addr) {
    asm volatile("ldmatrix.sync.aligned.m8n8.x4.shared.b16 {%0,%1,%2,%3}, [%4];"
        : "=r"(r[0]), "=r"(r[1]), "=r"(r[2]), "=r"(r[3]) : "r"(addr));
}
__device__ __forceinline__ void mma_fp16(float* c, const uint32_t* a, uint32_t b0, uint32_t b1) {
    asm volatile("mma.sync.aligned.m16n8k16.row.col.f32.f16.f16.f32 "
        "{%0,%1,%2,%3}, {%4,%5,%6,%7}, {%8,%9}, {%0,%1,%2,%3};"
        : "+f"(c[0]), "+f"(c[1]), "+f"(c[2]), "+f"(c[3])
        : "r"(a[0]), "r"(a[1]), "r"(a[2]), "r"(a[3]), "r"(b0), "r"(b1));
}

// ======================= split-fp16 HMMA GEMM core =======================
// terms==3: C = Ahi*Bhi^T + Alo*Bhi^T + Ahi*Blo^T   (QK logits only)
// terms==2: C = Ahi*Bhi^T + Alo*Bhi^T               (all weight GEMMs)
#define A_SLAB 16384
#define B_SLAB 8192
#define STAGE (2 * A_SLAB + 2 * B_SLAB)
#define MM_SMEM (2 * STAGE)

__device__ __forceinline__ void ld_stage(
    uint32_t st, const __half* Ahi, const __half* Alo,
    const __half* Bhi, const __half* Blo,
    int lda, int ldb, int k0, int tid, int terms)
{
#pragma unroll
    for (int it = 0; it < 4; it++) {
        int idx = it * 256 + tid;
        int row = idx >> 3, g = idx & 7;
        uint32_t off = row * 128 + ((g ^ (row & 7)) << 4);
        size_t s = (size_t)row * lda + k0 + g * 8;
        cp16(st + off, Ahi + s);
        cp16(st + A_SLAB + off, Alo + s);
    }
#pragma unroll
    for (int it = 0; it < 2; it++) {
        int idx = it * 256 + tid;
        int row = idx >> 3, g = idx & 7;
        uint32_t off = row * 128 + ((g ^ (row & 7)) << 4);
        size_t s = (size_t)row * ldb + k0 + g * 8;
        cp16(st + 2 * A_SLAB + off, Bhi + s);
        if (terms == 3)
            cp16(st + 2 * A_SLAB + B_SLAB + off, Blo + s);
    }
}

__device__ __forceinline__ void mm_hmma(
    const __half* __restrict__ Ahi, const __half* __restrict__ Alo, int lda,
    const __half* __restrict__ Bhi, const __half* __restrict__ Blo, int ldb,
    float* __restrict__ C, int ldc, int nk, float scale, int terms)
{
    extern __shared__ char smem[];
    const uint32_t sb = smem_u32(smem);
    const int tid = threadIdx.x, lane = tid & 31, wid = tid >> 5;
    const int wm = wid & 3, wn = wid >> 2;

    float c[2][4][4];
#pragma unroll
    for (int i = 0; i < 2; i++)
#pragma unroll
        for (int j = 0; j < 4; j++)
#pragma unroll
            for (int q = 0; q < 4; q++) c[i][j][q] = 0.f;

    ld_stage(sb, Ahi, Alo, Bhi, Blo, lda, ldb, 0, tid, terms); cp_commit();
    ld_stage(sb + STAGE, Ahi, Alo, Bhi, Blo, lda, ldb, 64, tid, terms); cp_commit();

    const int axor = lane & 7;
    for (int ck = 0; ck < nk; ck++) {
        if (ck == nk - 1) cp_wait0(); else cp_wait1();
        __syncthreads();
        const uint32_t st = sb + (ck & 1) * STAGE;
#pragma unroll
        for (int k16 = 0; k16 < 4; k16++) {
            uint32_t ah[2][4], al[2][4], bh[2][4], bl[2][4];
#pragma unroll
            for (int i = 0; i < 2; i++) {
                int arow = wm * 32 + i * 16 + (lane & 15);
                uint32_t ad = st + (uint32_t)(arow * 128)
                            + (uint32_t)(((2 * k16 + (lane >> 4)) ^ axor) << 4);
                ldsm4(ah[i], ad);
                ldsm4(al[i], ad + A_SLAB);
            }
#pragma unroll
            for (int j4 = 0; j4 < 2; j4++) {
                int brow = wn * 32 + j4 * 16 + ((lane >> 4) << 3) + (lane & 7);
                uint32_t bd = st + 2 * A_SLAB + (uint32_t)(brow * 128)
                            + (uint32_t)(((2 * k16 + ((lane >> 3) & 1)) ^ axor) << 4);
                ldsm4(bh[j4], bd);
                if (terms == 3) ldsm4(bl[j4], bd + B_SLAB);
            }
#pragma unroll
            for (int i = 0; i < 2; i++)
#pragma unroll
                for (int j4 = 0; j4 < 2; j4++) {
                    mma_fp16(c[i][2 * j4],     ah[i], bh[j4][0], bh[j4][1]);
                    mma_fp16(c[i][2 * j4 + 1], ah[i], bh[j4][2], bh[j4][3]);
                }
#pragma unroll
            for (int i = 0; i < 2; i++)
#pragma unroll
                for (int j4 = 0; j4 < 2; j4++) {
                    mma_fp16(c[i][2 * j4],     al[i], bh[j4][0], bh[j4][1]);
                    mma_fp16(c[i][2 * j4 + 1], al[i], bh[j4][2], bh[j4][3]);
                }
            if (terms == 3) {
#pragma unroll
                for (int i = 0; i < 2; i++)
#pragma unroll
                    for (int j4 = 0; j4 < 2; j4++) {
                        mma_fp16(c[i][2 * j4],     ah[i], bl[j4][0], bl[j4][1]);
                        mma_fp16(c[i][2 * j4 + 1], ah[i], bl[j4][2], bl[j4][3]);
                    }
            }
        }
        __syncthreads();
        if (ck + 2 < nk) {
            ld_stage(st, Ahi, Alo, Bhi, Blo, lda, ldb, (ck + 2) * 64, tid, terms);
            cp_commit();
        }
    }

    const int r0 = wm * 32 + (lane >> 2);
    const int c0 = wn * 32 + (lane & 3) * 2;
#pragma unroll
    for (int i = 0; i < 2; i++)
#pragma unroll
        for (int j = 0; j < 4; j++) {
            float2 v0 = { c[i][j][0] * scale, c[i][j][1] * scale };
            float2 v1 = { c[i][j][2] * scale, c[i][j][3] * scale };
            *(float2*)&C[(size_t)(r0 + i * 16) * ldc + c0 + j * 8] = v0;
            *(float2*)&C[(size_t)(r0 + i * 16 + 8) * ldc + c0 + j * 8] = v1;
        }
}

// ======================= conversion fp32 -> fp16 (hi, optional lo) =======================
#define X4 (SEQ * DMODEL / 4)
#define W4 (DMODEL * DMODEL / 4)

__device__ __forceinline__ void cvt_one(const float* src, __half* hi, __half* lo,
                                        long long r, bool write_lo)
{
    float4 v = ((const float4*)src)[r];
    __half h0 = __float2half(v.x), h1 = __float2half(v.y);
    __half h2 = __float2half(v.z), h3 = __float2half(v.w);
    __half2 H01; H01.x = h0; H01.y = h1;
    __half2 H23; H23.x = h2; H23.y = h3;
    *(__half2*)(hi + 4 * (size_t)r)     = H01;
    *(__half2*)(hi + 4 * (size_t)r + 2) = H23;
    if (write_lo) {
        __half2 L01, L23;
        L01.x = __float2half(v.x - __half2float(h0));
        L01.y = __float2half(v.y - __half2float(h1));
        L23.x = __float2half(v.z - __half2float(h2));
        L23.y = __float2half(v.w - __half2float(h3));
        *(__half2*)(lo + 4 * (size_t)r)     = L01;
        *(__half2*)(lo + 4 * (size_t)r + 2) = L23;
    }
}

// X (hi+lo), Wq, Wk (hi only)
__global__ __launch_bounds__(256) void cvt_main_kernel(
    const float* __restrict__ X, const float* __restrict__ Wq,
    const float* __restrict__ Wk)
{
    long long i = (long long)blockIdx.x * 256 + threadIdx.x;
    if (i < X4)                        cvt_one(X,  g_Xhi,    g_Xlo, i, true);
    else if ((i -= X4) < W4)           cvt_one(Wq, g_Whi[0], 0, i, false);
    else if ((i -= W4) < W4)           cvt_one(Wk, g_Whi[1], 0, i, false);
}

// Wv, Wo (hi only)
__global__ __launch_bounds__(256) void cvt_aux_kernel(
    const float* __restrict__ Wv, const float* __restrict__ Wo)
{
    long long i = (long long)blockIdx.x * 256 + threadIdx.x;
    if (i < W4)                        cvt_one(Wv, g_Whi[2], 0, i, false);
    else if ((i -= W4) < W4)           cvt_one(Wo, g_Whi[3], 0, i, false);
}

// ======================= GEMM wrappers =======================
__global__ __launch_bounds__(256, 2) void mm_qkproj_kernel()
{
    const int z = blockIdx.z;            // 0: Q, 1: K  (2-term: W residual dropped)
    const int m0 = blockIdx.y * 128, n0 = blockIdx.x * 64;
    float* O = (z == 0) ? g_Q : g_K;
    mm_hmma(g_Xhi + (size_t)m0 * DMODEL, g_Xlo + (size_t)m0 * DMODEL, DMODEL,
            g_Whi[z] + (size_t)n0 * DMODEL, 0, DMODEL,
            O + (size_t)m0 * DMODEL + n0, DMODEL, DMODEL / 64, 1.0f, 2);
}

__global__ __launch_bounds__(256, 2) void mm_v_kernel()
{
    const int m0 = blockIdx.y * 128, n0 = blockIdx.x * 64;
    mm_hmma(g_Xhi + (size_t)m0 * DMODEL, g_Xlo + (size_t)m0 * DMODEL, DMODEL,
            g_Whi[2] + (size_t)n0 * DMODEL, 0, DMODEL,
            g_V + (size_t)m0 * DMODEL + n0, DMODEL, DMODEL / 64, 1.0f, 2);
}

__global__ __launch_bounds__(256, 2) void mm_o_kernel(float* __restrict__ out)
{
    const int m0 = blockIdx.y * 128, n0 = blockIdx.x * 64;
    mm_hmma(g_AOhi + (size_t)m0 * DMODEL, g_AOlo + (size_t)m0 * DMODEL, DMODEL,
            g_Whi[3] + (size_t)n0 * DMODEL, 0, DMODEL,
            out + (size_t)m0 * DMODEL + n0, DMODEL, DMODEL / 64, 1.0f, 2);
}

__global__ __launch_bounds__(256, 2) void mm_qk_kernel()
{
    const int h = blockIdx.z;
    const int m0 = blockIdx.y * 128, n0 = blockIdx.x * 64;
    if (n0 > m0 + 127) return;
    mm_hmma(g_Qhi + (size_t)m0 * DMODEL + h * HD, g_Qlo + (size_t)m0 * DMODEL + h * HD, DMODEL,
            g_Khi + (size_t)n0 * DMODEL + h * HD, g_Klo + (size_t)n0 * DMODEL + h * HD, DMODEL,
            g_P + (size_t)h * SEQ * SEQ + (size_t)m0 * SEQ + n0, SEQ,
            HD / 64, 0.08838834764831845f, 3);
}

// ======================= RoPE: fp32 Q/K -> roped fp16 hi/lo =======================
__global__ void rope_kernel()
{
    int idx = blockIdx.x * blockDim.x + threadIdx.x;
    const float* src = blockIdx.y ? g_K : g_Q;
    __half* hi = blockIdx.y ? g_Khi : g_Qhi;
    __half* lo = blockIdx.y ? g_Klo : g_Qlo;
    int p = idx & 63;
    int h = (idx >> 6) & 31;
    int s = idx >> 11;
    float inv = 1.0f / powf(10000.0f, (float)(2 * p) * (1.0f / 128.0f));
    float ang = (float)s * inv;
    float sn, c;
    sincosf(ang, &sn, &c);
    size_t b = (size_t)s * DMODEL + h * HD + p;
    float q0 = src[b], q1 = src[b + 64];
    float r0 = q0 * c - q1 * sn;
    float r1 = q1 * c + q0 * sn;
    __half h0 = __float2half(r0);
    __half h1 = __float2half(r1);
    hi[b] = h0;      lo[b]      = __float2half(r0 - __half2float(h0));
    hi[b + 64] = h1; lo[b + 64] = __float2half(r1 - __half2float(h1));
}

// ======================= softmax (probs P0, zero above diagonal) =======================
__global__ __launch_bounds__(256) void softmax_kernel()
{
    const int i = blockIdx.x, h = blockIdx.y;
    float* row = g_P + (size_t)h * SEQ * SEQ + (size_t)i * SEQ;
    const int n = i + 1;
    const int tid = threadIdx.x;
    const int lane = tid & 31, wid = tid >> 5;
    __shared__ float red[16];

    float m = -FLT_MAX;
    for (int j = tid; j < n; j += 256) m = fmaxf(m, row[j]);
#pragma unroll
    for (int o = 16; o; o >>= 1) m = fmaxf(m, __shfl_xor_sync(0xffffffffu, m, o));
    if (lane == 0) red[wid] = m;
    __syncthreads();
    m = red[0];
#pragma unroll
    for (int w = 1; w < 8; w++) m = fmaxf(m, red[w]);

    float s = 0.f;
    for (int j = tid; j < n; j += 256) s += expf(row[j] - m);
#pragma unroll
    for (int o = 16; o; o >>= 1) s += __shfl_xor_sync(0xffffffffu, s, o);
    if (lane == 0) red[8 + wid] = s;
    __syncthreads();
    float tot = 0.f;
#pragma unroll
    for (int w = 0; w < 8; w++) tot += red[8 + w];
    const float invs = 1.0f / tot;

    for (int j = tid; j < SEQ; j += 256)
        row[j] = (j < n) ? expf(row[j] - m) * invs : 0.f;
}

// ======================= H2O sequential scan =======================
__global__ __launch_bounds__(128) void scan_kernel()
{
    const int h = blockIdx.x;
    const int tid = threadIdx.x;
    const int lane = tid & 31, wid = tid >> 5;
    __shared__ float acc[SEQ];
    __shared__ float rowbuf[2][SEQ];
    __shared__ int   lst[128];
    __shared__ float skey[128];
    __shared__ unsigned mw[32];
    const float* P = g_P + (size_t)h * SEQ * SEQ;
    unsigned* MB = g_M + h * SEQ * (SEQ / 32);

    for (int j = tid; j < SEQ; j += 128) acc[j] = 0.f;
    __syncthreads();
    if (tid < HB) {
        float s = 0.f;
        for (int i = 0; i < HB; i++) s += P[(size_t)i * SEQ + tid];
        acc[tid] = s;
        lst[tid] = tid;
    }
    {
        uint32_t dst = smem_u32(&rowbuf[HB & 1][0]);
        const float* src = P + (size_t)HB * SEQ;
        for (int g = tid; g < SEQ / 4; g += 128) cp16(dst + g * 16, src + g * 4);
        cp_commit();
    }
    cp_wait0();
    __syncthreads();

    int cnt = HB;
    for (int t = HB; t < SEQ; t++) {
        if (t + 1 < SEQ) {
            uint32_t dst = smem_u32(&rowbuf[(t + 1) & 1][0]);
            const float* src = P + (size_t)(t + 1) * SEQ;
            for (int g = tid; g < SEQ / 4; g += 128) cp16(dst + g * 16, src + g * 4);
            cp_commit();
        }
        if (wid == 0) {
            const float* Prow = rowbuf[t & 1];
            for (int p = lane; p < cnt; p += 32) skey[p] = acc[lst[p]];
            __syncwarp();

            const int r = cnt - (HB - 1);
            for (int rep = 0; rep < r; rep++) {
                float bv = FLT_MAX; int bidx = -1; int bpos = 0;
                for (int p = lane; p < cnt; p += 32) {
                    float v = skey[p]; int ix = lst[p];
                    if (v < bv || (v == bv && ix > bidx)) { bv = v; bidx = ix; bpos = p; }
                }
#pragma unroll
                for (int o = 16; o; o >>= 1) {
                    float ov = __shfl_down_sync(0xffffffffu, bv, o);
                    int   oi = __shfl_down_sync(0xffffffffu, bidx, o);
                    int   op = __shfl_down_sync(0xffffffffu, bpos, o);
                    if (ov < bv || (ov == bv && oi > bidx)) { bv = ov; bidx = oi; bpos = op; }
                }
                bidx = __shfl_sync(0xffffffffu, bidx, 0);
                bpos = __shfl_sync(0xffffffffu, bpos, 0);
                if (bidx >= 4) {
                    if (lane == 0) {
                        acc[bidx] = 0.f;
                        lst[bpos]  = lst[cnt - 1];
                        skey[bpos] = skey[cnt - 1];
                    }
                    cnt--;
                } else {
                    if (lane == 0) skey[bpos] = FLT_MAX;
                }
                __syncwarp();
            }
            if (lane == 0) lst[cnt] = t;
            cnt++;
            mw[lane] = 0u;
            __syncwarp();
            for (int p = lane; p < cnt; p += 32) {
                int ix = lst[p];
                acc[ix] += Prow[ix];
                atomicOr(&mw[ix >> 5], 1u << (ix & 31));
            }
            __syncwarp();
            MB[t * 32 + lane] = mw[lane];
        }
        cp_wait0();
        __syncthreads();
    }
}

// ======================= masked renorm softmax + P@V (writes AO hi/lo) =======================
__global__ __launch_bounds__(128) void pv_kernel()
{
    const int h = blockIdx.y;
    const int tid = threadIdx.x;
    const int lane = tid & 31, wid = tid >> 5;
    __shared__ float pv[224];
    __shared__ int   pj[224];
    __shared__ int   wbase[4];
    __shared__ float wsum[4];
    __shared__ int   s_cnt;
    __shared__ float s_sum;

    for (int u8 = 0; u8 < 8; u8++) {
        const int s = blockIdx.x * 8 + u8;
        const float* Prow = g_P + (size_t)h * SEQ * SEQ + (size_t)s * SEQ;
        const unsigned* mb = g_M + (h * SEQ + s) * (SEQ / 32);

        float pr[8]; bool al[8];
        int c = 0; float lsum = 0.f;
        const int j0 = tid * 8;
#pragma unroll
        for (int u = 0; u < 8; u++) {
            const int j = j0 + u;
            bool a;
            if (s < HB) a = (j <= s);
            else        a = (j <= s) && ((j + RB >= s) || ((mb[j >> 5] >> (j & 31)) & 1u));
            float val = a ? Prow[j] : 0.f;
            al[u] = a; pr[u] = val;
            if (a) { c++; lsum += val; }
        }
        int inc = c;
#pragma unroll
        for (int o = 1; o < 32; o <<= 1) {
            int v = __shfl_up_sync(0xffffffffu, inc, o);
            if (lane >= o) inc += v;
        }
        float ws = lsum;
#pragma unroll
        for (int o = 16; o; o >>= 1) ws += __shfl_xor_sync(0xffffffffu, ws, o);
        if (lane == 31) wbase[wid] = inc;
        if (lane == 0)  wsum[wid] = ws;
        __syncthreads();
        if (tid == 0) {
            int tot = 0;
#pragma unroll
            for (int w = 0; w < 4; w++) { int b = wbase[w]; wbase[w] = tot; tot += b; }
            s_cnt = tot;
            s_sum = wsum[0] + wsum[1] + wsum[2] + wsum[3];
        }
        __syncthreads();
        int k = wbase[wid] + inc - c;
#pragma unroll
        for (int u = 0; u < 8; u++)
            if (al[u]) { pv[k] = pr[u]; pj[k] = j0 + u; k++; }
        __syncthreads();

        const int cnt = s_cnt;
        const float inv = 1.0f / s_sum;
        const float* Vh = g_V + h * HD + tid;
        float acc = 0.f;
        int m2 = 0;
        for (; m2 + 4 <= cnt; m2 += 4) {
            acc += pv[m2 + 0] * Vh[(size_t)pj[m2 + 0] * DMODEL];
            acc += pv[m2 + 1] * Vh[(size_t)pj[m2 + 1] * DMODEL];
            acc += pv[m2 + 2] * Vh[(size_t)pj[m2 + 2] * DMODEL];
            acc += pv[m2 + 3] * Vh[(size_t)pj[m2 + 3] * DMODEL];
        }
        for (; m2 < cnt; m2++) acc += pv[m2] * Vh[(size_t)pj[m2] * DMODEL];

        float v = acc * inv;
        __half hv = __float2half(v);
        size_t oi = (size_t)s * DMODEL + h * HD + tid;
        g_AOhi[oi] = hv;
        g_AOlo[oi] = __float2half(v - __half2float(hv));
        __syncthreads();
    }
}

// ======================= launch (fork-join streams inside capture) =======================
extern "C" void kernel_launch(void* const* d_in, const int* in_sizes, int n_in,
                              void* d_out, int out_size)
{
    const float* X  = (const float*)d_in[0];
    const float* Wq = (const float*)d_in[2];
    const float* Wk = (const float*)d_in[3];
    const float* Wv = (const float*)d_in[4];
    const float* Wo = (const float*)d_in[5];
    float* out = (float*)d_out;

    static cudaStream_t s_aux = 0;
    static cudaEvent_t ev_begin = 0, ev_xcvt = 0, ev_vdone = 0;
    if (!s_aux) {
        int lo_p, hi_p;
        cudaDeviceGetStreamPriorityRange(&lo_p, &hi_p);
        cudaStreamCreateWithPriority(&s_aux, cudaStreamNonBlocking, lo_p);
        cudaEventCreateWithFlags(&ev_begin, cudaEventDisableTiming);
        cudaEventCreateWithFlags(&ev_xcvt,  cudaEventDisableTiming);
        cudaEventCreateWithFlags(&ev_vdone, cudaEventDisableTiming);
    }

    cudaFuncSetAttribute(mm_qkproj_kernel, cudaFuncAttributeMaxDynamicSharedMemorySize, MM_SMEM);
    cudaFuncSetAttribute(mm_v_kernel,      cudaFuncAttributeMaxDynamicSharedMemorySize, MM_SMEM);
    cudaFuncSetAttribute(mm_qk_kernel,     cudaFuncAttributeMaxDynamicSharedMemorySize, MM_SMEM);
    cudaFuncSetAttribute(mm_o_kernel,      cudaFuncAttributeMaxDynamicSharedMemorySize, MM_SMEM);

    cudaEventRecord(ev_begin, 0);
    cudaStreamWaitEvent(s_aux, ev_begin, 0);

    cvt_aux_kernel<<<(2 * W4 + 255) / 256, 256, 0, s_aux>>>(Wv, Wo);

    cvt_main_kernel<<<(X4 + 2 * W4 + 255) / 256, 256>>>(X, Wq, Wk);
    cudaEventRecord(ev_xcvt, 0);

    mm_qkproj_kernel<<<dim3(DMODEL / 64, SEQ / 128, 2), 256, MM_SMEM>>>();
    rope_kernel<<<dim3((SEQ * NH * 64) / 256, 2), 256>>>();
    mm_qk_kernel<<<dim3(SEQ / 64, SEQ / 128, NH), 256, MM_SMEM>>>();
    softmax_kernel<<<dim3(SEQ, NH), 256>>>();
    scan_kernel<<<NH, 128>>>();

    cudaStreamWaitEvent(s_aux, ev_xcvt, 0);
    mm_v_kernel<<<dim3(DMODEL / 64, SEQ / 128), 256, MM_SMEM, s_aux>>>();
    cudaEventRecord(ev_vdone, s_aux);

    cudaStreamWaitEvent(0, ev_vdone, 0);
    pv_kernel<<<dim3(SEQ / 8, NH), 128>>>();
    mm_o_kernel<<<dim3(DMODEL / 64, SEQ / 128), 256, MM_SMEM>>>(out);
}

// round 12
// speedup vs baseline: 1.2760x; 1.0752x over previous
#include <cuda_runtime.h>
#include <cuda_fp16.h>
#include <math.h>
#include <float.h>
#include <stdint.h>

#define SEQ 1024
#define DMODEL 4096
#define NH 32
#define HD 128
#define HB 102
#define RB 102

// ======================= static device scratch =======================
__device__ __align__(256) float g_Q[SEQ * DMODEL];
__device__ __align__(256) float g_K[SEQ * DMODEL];
__device__ __align__(256) float g_V[SEQ * DMODEL];
__device__ __align__(256) float g_P[(size_t)NH * SEQ * SEQ];
__device__ unsigned g_M[NH * SEQ * (SEQ / 32)];
__device__ __align__(256) __half g_Xhi[SEQ * DMODEL], g_Xlo[SEQ * DMODEL];
__device__ __align__(256) __half g_Whi[4][DMODEL * DMODEL];
__device__ __align__(256) __half g_Qhi[SEQ * DMODEL], g_Qlo[SEQ * DMODEL];
__device__ __align__(256) __half g_Khi[SEQ * DMODEL], g_Klo[SEQ * DMODEL];
__device__ __align__(256) __half g_AOhi[SEQ * DMODEL], g_AOlo[SEQ * DMODEL];

// ======================= helpers =======================
__device__ __forceinline__ uint32_t smem_u32(const void* p) {
    uint32_t a;
    asm("{ .reg .u64 t; cvta.to.shared.u64 t, %1; cvt.u32.u64 %0, t; }" : "=r"(a) : "l"(p));
    return a;
}
__device__ __forceinline__ void cp16(uint32_t dst, const void* src) {
    asm volatile("cp.async.cg.shared.global [%0], [%1], 16;" :: "r"(dst), "l"(src));
}
__device__ __forceinline__ void cp_commit() { asm volatile("cp.async.commit_group;" ::: "memory"); }
__device__ __forceinline__ void cp_wait1() { asm volatile("cp.async.wait_group 1;" ::: "memory"); }
__device__ __forceinline__ void cp_wait0() { asm volatile("cp.async.wait_group 0;" ::: "memory"); }

__device__ __forceinline__ void ldsm4(uint32_t* r, uint32_t addr) {
    asm volatile("ldmatrix.sync.aligned.m8n8.x4.shared.b16 {%0,%1,%2,%3}, [%4];"
        : "=r"(r[0]), "=r"(r[1]), "=r"(r[2]), "=r"(r[3]) : "r"(addr));
}
__device__ __forceinline__ void mma_fp16(float* c, const uint32_t* a, uint32_t b0, uint32_t b1) {
    asm volatile("mma.sync.aligned.m16n8k16.row.col.f32.f16.f16.f32 "
        "{%0,%1,%2,%3}, {%4,%5,%6,%7}, {%8,%9}, {%0,%1,%2,%3};"
        : "+f"(c[0]), "+f"(c[1]), "+f"(c[2]), "+f"(c[3])
        : "r"(a[0]), "r"(a[1]), "r"(a[2]), "r"(a[3]), "r"(b0), "r"(b1));
}

// ======================= split-fp16 HMMA GEMM core =======================
#define A_SLAB 16384
#define B_SLAB 8192
#define STAGE (2 * A_SLAB + 2 * B_SLAB)
#define MM_SMEM (2 * STAGE)

__device__ __forceinline__ void ld_stage(
    uint32_t st, const __half* Ahi, const __half* Alo,
    const __half* Bhi, const __half* Blo,
    int lda, int ldb, int k0, int tid, int terms)
{
#pragma unroll
    for (int it = 0; it < 4; it++) {
        int idx = it * 256 + tid;
        int row = idx >> 3, g = idx & 7;
        uint32_t off = row * 128 + ((g ^ (row & 7)) << 4);
        size_t s = (size_t)row * lda + k0 + g * 8;
        cp16(st + off, Ahi + s);
        cp16(st + A_SLAB + off, Alo + s);
    }
#pragma unroll
    for (int it = 0; it < 2; it++) {
        int idx = it * 256 + tid;
        int row = idx >> 3, g = idx & 7;
        uint32_t off = row * 128 + ((g ^ (row & 7)) << 4);
        size_t s = (size_t)row * ldb + k0 + g * 8;
        cp16(st + 2 * A_SLAB + off, Bhi + s);
        if (terms == 3)
            cp16(st + 2 * A_SLAB + B_SLAB + off, Blo + s);
    }
}

__device__ __forceinline__ void mm_hmma(
    const __half* __restrict__ Ahi, const __half* __restrict__ Alo, int lda,
    const __half* __restrict__ Bhi, const __half* __restrict__ Blo, int ldb,
    float* __restrict__ C, int ldc, int nk, float scale, int terms)
{
    extern __shared__ char smem[];
    const uint32_t sb = smem_u32(smem);
    const int tid = threadIdx.x, lane = tid & 31, wid = tid >> 5;
    const int wm = wid & 3, wn = wid >> 2;

    float c[2][4][4];
#pragma unroll
    for (int i = 0; i < 2; i++)
#pragma unroll
        for (int j = 0; j < 4; j++)
#pragma unroll
            for (int q = 0; q < 4; q++) c[i][j][q] = 0.f;

    ld_stage(sb, Ahi, Alo, Bhi, Blo, lda, ldb, 0, tid, terms); cp_commit();
    ld_stage(sb + STAGE, Ahi, Alo, Bhi, Blo, lda, ldb, 64, tid, terms); cp_commit();

    const int axor = lane & 7;
    for (int ck = 0; ck < nk; ck++) {
        if (ck == nk - 1) cp_wait0(); else cp_wait1();
        __syncthreads();
        const uint32_t st = sb + (ck & 1) * STAGE;
#pragma unroll
        for (int k16 = 0; k16 < 4; k16++) {
            uint32_t ah[2][4], al[2][4], bh[2][4], bl[2][4];
#pragma unroll
            for (int i = 0; i < 2; i++) {
                int arow = wm * 32 + i * 16 + (lane & 15);
                uint32_t ad = st + (uint32_t)(arow * 128)
                            + (uint32_t)(((2 * k16 + (lane >> 4)) ^ axor) << 4);
                ldsm4(ah[i], ad);
                ldsm4(al[i], ad + A_SLAB);
            }
#pragma unroll
            for (int j4 = 0; j4 < 2; j4++) {
                int brow = wn * 32 + j4 * 16 + ((lane >> 4) << 3) + (lane & 7);
                uint32_t bd = st + 2 * A_SLAB + (uint32_t)(brow * 128)
                            + (uint32_t)(((2 * k16 + ((lane >> 3) & 1)) ^ axor) << 4);
                ldsm4(bh[j4], bd);
                if (terms == 3) ldsm4(bl[j4], bd + B_SLAB);
            }
#pragma unroll
            for (int i = 0; i < 2; i++)
#pragma unroll
                for (int j4 = 0; j4 < 2; j4++) {
                    mma_fp16(c[i][2 * j4],     ah[i], bh[j4][0], bh[j4][1]);
                    mma_fp16(c[i][2 * j4 + 1], ah[i], bh[j4][2], bh[j4][3]);
                }
#pragma unroll
            for (int i = 0; i < 2; i++)
#pragma unroll
                for (int j4 = 0; j4 < 2; j4++) {
                    mma_fp16(c[i][2 * j4],     al[i], bh[j4][0], bh[j4][1]);
                    mma_fp16(c[i][2 * j4 + 1], al[i], bh[j4][2], bh[j4][3]);
                }
            if (terms == 3) {
#pragma unroll
                for (int i = 0; i < 2; i++)
#pragma unroll
                    for (int j4 = 0; j4 < 2; j4++) {
                        mma_fp16(c[i][2 * j4],     ah[i], bl[j4][0], bl[j4][1]);
                        mma_fp16(c[i][2 * j4 + 1], ah[i], bl[j4][2], bl[j4][3]);
                    }
            }
        }
        __syncthreads();
        if (ck + 2 < nk) {
            ld_stage(st, Ahi, Alo, Bhi, Blo, lda, ldb, (ck + 2) * 64, tid, terms);
            cp_commit();
        }
    }

    const int r0 = wm * 32 + (lane >> 2);
    const int c0 = wn * 32 + (lane & 3) * 2;
#pragma unroll
    for (int i = 0; i < 2; i++)
#pragma unroll
        for (int j = 0; j < 4; j++) {
            float2 v0 = { c[i][j][0] * scale, c[i][j][1] * scale };
            float2 v1 = { c[i][j][2] * scale, c[i][j][3] * scale };
            *(float2*)&C[(size_t)(r0 + i * 16) * ldc + c0 + j * 8] = v0;
            *(float2*)&C[(size_t)(r0 + i * 16 + 8) * ldc + c0 + j * 8] = v1;
        }
}

// ======================= conversion fp32 -> fp16 (hi, optional lo) =======================
#define X4 (SEQ * DMODEL / 4)
#define W4 (DMODEL * DMODEL / 4)

__device__ __forceinline__ void cvt_one(const float* src, __half* hi, __half* lo,
                                        long long r, bool write_lo)
{
    float4 v = ((const float4*)src)[r];
    __half h0 = __float2half(v.x), h1 = __float2half(v.y);
    __half h2 = __float2half(v.z), h3 = __float2half(v.w);
    __half2 H01; H01.x = h0; H01.y = h1;
    __half2 H23; H23.x = h2; H23.y = h3;
    *(__half2*)(hi + 4 * (size_t)r)     = H01;
    *(__half2*)(hi + 4 * (size_t)r + 2) = H23;
    if (write_lo) {
        __half2 L01, L23;
        L01.x = __float2half(v.x - __half2float(h0));
        L01.y = __float2half(v.y - __half2float(h1));
        L23.x = __float2half(v.z - __half2float(h2));
        L23.y = __float2half(v.w - __half2float(h3));
        *(__half2*)(lo + 4 * (size_t)r)     = L01;
        *(__half2*)(lo + 4 * (size_t)r + 2) = L23;
    }
}

__global__ __launch_bounds__(256) void cvt_main_kernel(
    const float* __restrict__ X, const float* __restrict__ Wq,
    const float* __restrict__ Wk)
{
    long long i = (long long)blockIdx.x * 256 + threadIdx.x;
    if (i < X4)                        cvt_one(X,  g_Xhi,    g_Xlo, i, true);
    else if ((i -= X4) < W4)           cvt_one(Wq, g_Whi[0], 0, i, false);
    else if ((i -= W4) < W4)           cvt_one(Wk, g_Whi[1], 0, i, false);
}

__global__ __launch_bounds__(256) void cvt_aux_kernel(
    const float* __restrict__ Wv, const float* __restrict__ Wo)
{
    long long i = (long long)blockIdx.x * 256 + threadIdx.x;
    if (i < W4)                        cvt_one(Wv, g_Whi[2], 0, i, false);
    else if ((i -= W4) < W4)           cvt_one(Wo, g_Whi[3], 0, i, false);
}

// ======================= GEMM wrappers =======================
__global__ __launch_bounds__(256, 2) void mm_qkproj_kernel()
{
    const int z = blockIdx.z;
    const int m0 = blockIdx.y * 128, n0 = blockIdx.x * 64;
    float* O = (z == 0) ? g_Q : g_K;
    mm_hmma(g_Xhi + (size_t)m0 * DMODEL, g_Xlo + (size_t)m0 * DMODEL, DMODEL,
            g_Whi[z] + (size_t)n0 * DMODEL, 0, DMODEL,
            O + (size_t)m0 * DMODEL + n0, DMODEL, DMODEL / 64, 1.0f, 2);
}

__global__ __launch_bounds__(256, 2) void mm_v_kernel()
{
    const int m0 = blockIdx.y * 128, n0 = blockIdx.x * 64;
    mm_hmma(g_Xhi + (size_t)m0 * DMODEL, g_Xlo + (size_t)m0 * DMODEL, DMODEL,
            g_Whi[2] + (size_t)n0 * DMODEL, 0, DMODEL,
            g_V + (size_t)m0 * DMODEL + n0, DMODEL, DMODEL / 64, 1.0f, 2);
}

__global__ __launch_bounds__(256, 2) void mm_o_kernel(float* __restrict__ out, int yofs)
{
    const int m0 = (blockIdx.y + yofs) * 128, n0 = blockIdx.x * 64;
    mm_hmma(g_AOhi + (size_t)m0 * DMODEL, g_AOlo + (size_t)m0 * DMODEL, DMODEL,
            g_Whi[3] + (size_t)n0 * DMODEL, 0, DMODEL,
            out + (size_t)m0 * DMODEL + n0, DMODEL, DMODEL / 64, 1.0f, 2);
}

__global__ __launch_bounds__(256, 2) void mm_qk_kernel(int hofs)
{
    const int h = blockIdx.z + hofs;
    const int m0 = blockIdx.y * 128, n0 = blockIdx.x * 64;
    if (n0 > m0 + 127) return;
    mm_hmma(g_Qhi + (size_t)m0 * DMODEL + h * HD, g_Qlo + (size_t)m0 * DMODEL + h * HD, DMODEL,
            g_Khi + (size_t)n0 * DMODEL + h * HD, g_Klo + (size_t)n0 * DMODEL + h * HD, DMODEL,
            g_P + (size_t)h * SEQ * SEQ + (size_t)m0 * SEQ + n0, SEQ,
            HD / 64, 0.08838834764831845f, 3);
}

// ======================= RoPE =======================
__global__ void rope_kernel()
{
    int idx = blockIdx.x * blockDim.x + threadIdx.x;
    const float* src = blockIdx.y ? g_K : g_Q;
    __half* hi = blockIdx.y ? g_Khi : g_Qhi;
    __half* lo = blockIdx.y ? g_Klo : g_Qlo;
    int p = idx & 63;
    int h = (idx >> 6) & 31;
    int s = idx >> 11;
    float inv = 1.0f / powf(10000.0f, (float)(2 * p) * (1.0f / 128.0f));
    float ang = (float)s * inv;
    float sn, c;
    sincosf(ang, &sn, &c);
    size_t b = (size_t)s * DMODEL + h * HD + p;
    float q0 = src[b], q1 = src[b + 64];
    float r0 = q0 * c - q1 * sn;
    float r1 = q1 * c + q0 * sn;
    __half h0 = __float2half(r0);
    __half h1 = __float2half(r1);
    hi[b] = h0;      lo[b]      = __float2half(r0 - __half2float(h0));
    hi[b + 64] = h1; lo[b + 64] = __float2half(r1 - __half2float(h1));
}

// ======================= softmax (per head-group) =======================
__global__ __launch_bounds__(256) void softmax_kernel(int hofs)
{
    const int i = blockIdx.x, h = blockIdx.y + hofs;
    float* row = g_P + (size_t)h * SEQ * SEQ + (size_t)i * SEQ;
    const int n = i + 1;
    const int tid = threadIdx.x;
    const int lane = tid & 31, wid = tid >> 5;
    __shared__ float red[16];

    float m = -FLT_MAX;
    for (int j = tid; j < n; j += 256) m = fmaxf(m, row[j]);
#pragma unroll
    for (int o = 16; o; o >>= 1) m = fmaxf(m, __shfl_xor_sync(0xffffffffu, m, o));
    if (lane == 0) red[wid] = m;
    __syncthreads();
    m = red[0];
#pragma unroll
    for (int w = 1; w < 8; w++) m = fmaxf(m, red[w]);

    float s = 0.f;
    for (int j = tid; j < n; j += 256) s += expf(row[j] - m);
#pragma unroll
    for (int o = 16; o; o >>= 1) s += __shfl_xor_sync(0xffffffffu, s, o);
    if (lane == 0) red[8 + wid] = s;
    __syncthreads();
    float tot = 0.f;
#pragma unroll
    for (int w = 0; w < 8; w++) tot += red[8 + w];
    const float invs = 1.0f / tot;

    for (int j = tid; j < SEQ; j += 256)
        row[j] = (j < n) ? expf(row[j] - m) * invs : 0.f;
}

// ======================= H2O sequential scan (per head-group) =======================
// Candidate keys live in skey permanently (they ARE the accumulated scores);
// no per-iteration acc re-gather. Protected cols 0..3 use a skip bitmask
// instead of value clobbering. FP operations and order identical to before.
__global__ __launch_bounds__(128) void scan_kernel(int hofs)
{
    const int h = blockIdx.x + hofs;
    const int tid = threadIdx.x;
    const int lane = tid & 31, wid = tid >> 5;
    __shared__ float rowbuf[2][SEQ];
    __shared__ int   lst[128];
    __shared__ float skey[128];
    __shared__ unsigned mw[32];
    __shared__ unsigned skipm;
    const float* P = g_P + (size_t)h * SEQ * SEQ;
    unsigned* MB = g_M + h * SEQ * (SEQ / 32);

    // acc0 for cols < HB
    if (tid < HB) {
        float s = 0.f;
        for (int i = 0; i < HB; i++) s += P[(size_t)i * SEQ + tid];
        skey[tid] = s;
        lst[tid] = tid;
    }
    {
        uint32_t dst = smem_u32(&rowbuf[HB & 1][0]);
        const float* src = P + (size_t)HB * SEQ;
        for (int g = tid; g < SEQ / 4; g += 128) cp16(dst + g * 16, src + g * 4);
        cp_commit();
    }
    cp_wait0();
    __syncthreads();

    int cnt = HB;
    for (int t = HB; t < SEQ; t++) {
        if (t + 1 < SEQ) {
            uint32_t dst = smem_u32(&rowbuf[(t + 1) & 1][0]);
            const float* src = P + (size_t)(t + 1) * SEQ;
            for (int g = tid; g < SEQ / 4; g += 128) cp16(dst + g * 16, src + g * 4);
            cp_commit();
        }
        if (wid == 0) {
            const float* Prow = rowbuf[t & 1];
            if (lane == 0) skipm = 0u;
            __syncwarp();

            const int r = cnt - (HB - 1);
            for (int rep = 0; rep < r; rep++) {
                const unsigned sk = skipm;
                float bv = FLT_MAX; int bidx = -1; int bpos = 0;
                for (int p = lane; p < cnt; p += 32) {
                    int ix = lst[p];
                    if (ix < 4 && ((sk >> ix) & 1u)) continue;
                    float v = skey[p];
                    if (v < bv || (v == bv && ix > bidx)) { bv = v; bidx = ix; bpos = p; }
                }
#pragma unroll
                for (int o = 16; o; o >>= 1) {
                    float ov = __shfl_down_sync(0xffffffffu, bv, o);
                    int   oi = __shfl_down_sync(0xffffffffu, bidx, o);
                    int   op = __shfl_down_sync(0xffffffffu, bpos, o);
                    if (ov < bv || (ov == bv && oi > bidx)) { bv = ov; bidx = oi; bpos = op; }
                }
                bidx = __shfl_sync(0xffffffffu, bidx, 0);
                bpos = __shfl_sync(0xffffffffu, bpos, 0);
                if (bidx >= 4) {
                    if (lane == 0) {
                        lst[bpos]  = lst[cnt - 1];
                        skey[bpos] = skey[cnt - 1];
                    }
                    cnt--;
                } else {
                    if (lane == 0) skipm |= (1u << bidx);
                }
                __syncwarp();
            }
            if (lane == 0) { lst[cnt] = t; skey[cnt] = 0.f; }
            cnt++;
            mw[lane] = 0u;
            __syncwarp();
            for (int p = lane; p < cnt; p += 32) {
                int ix = lst[p];
                skey[p] += Prow[ix];
                atomicOr(&mw[ix >> 5], 1u << (ix & 31));
            }
            __syncwarp();
            MB[t * 32 + lane] = mw[lane];
        }
        cp_wait0();
        __syncthreads();
    }
}

// ======================= masked renorm softmax + P@V (row-half) =======================
__global__ __launch_bounds__(128) void pv_kernel(int bofs)
{
    const int h = blockIdx.y;
    const int tid = threadIdx.x;
    const int lane = tid & 31, wid = tid >> 5;
    __shared__ float pv[224];
    __shared__ int   pj[224];
    __shared__ int   wbase[4];
    __shared__ float wsum[4];
    __shared__ int   s_cnt;
    __shared__ float s_sum;

    for (int u8 = 0; u8 < 8; u8++) {
        const int s = (blockIdx.x + bofs) * 8 + u8;
        const float* Prow = g_P + (size_t)h * SEQ * SEQ + (size_t)s * SEQ;
        const unsigned* mb = g_M + (h * SEQ + s) * (SEQ / 32);

        float pr[8]; bool al[8];
        int c = 0; float lsum = 0.f;
        const int j0 = tid * 8;
#pragma unroll
        for (int u = 0; u < 8; u++) {
            const int j = j0 + u;
            bool a;
            if (s < HB) a = (j <= s);
            else        a = (j <= s) && ((j + RB >= s) || ((mb[j >> 5] >> (j & 31)) & 1u));
            float val = a ? Prow[j] : 0.f;
            al[u] = a; pr[u] = val;
            if (a) { c++; lsum += val; }
        }
        int inc = c;
#pragma unroll
        for (int o = 1; o < 32; o <<= 1) {
            int v = __shfl_up_sync(0xffffffffu, inc, o);
            if (lane >= o) inc += v;
        }
        float ws = lsum;
#pragma unroll
        for (int o = 16; o; o >>= 1) ws += __shfl_xor_sync(0xffffffffu, ws, o);
        if (lane == 31) wbase[wid] = inc;
        if (lane == 0)  wsum[wid] = ws;
        __syncthreads();
        if (tid == 0) {
            int tot = 0;
#pragma unroll
            for (int w = 0; w < 4; w++) { int b = wbase[w]; wbase[w] = tot; tot += b; }
            s_cnt = tot;
            s_sum = wsum[0] + wsum[1] + wsum[2] + wsum[3];
        }
        __syncthreads();
        int k = wbase[wid] + inc - c;
#pragma unroll
        for (int u = 0; u < 8; u++)
            if (al[u]) { pv[k] = pr[u]; pj[k] = j0 + u; k++; }
        __syncthreads();

        const int cnt = s_cnt;
        const float inv = 1.0f / s_sum;
        const float* Vh = g_V + h * HD + tid;
        float acc = 0.f;
        int m2 = 0;
        for (; m2 + 4 <= cnt; m2 += 4) {
            acc += pv[m2 + 0] * Vh[(size_t)pj[m2 + 0] * DMODEL];
            acc += pv[m2 + 1] * Vh[(size_t)pj[m2 + 1] * DMODEL];
            acc += pv[m2 + 2] * Vh[(size_t)pj[m2 + 2] * DMODEL];
            acc += pv[m2 + 3] * Vh[(size_t)pj[m2 + 3] * DMODEL];
        }
        for (; m2 < cnt; m2++) acc += pv[m2] * Vh[(size_t)pj[m2] * DMODEL];

        float v = acc * inv;
        __half hv = __float2half(v);
        size_t oi = (size_t)s * DMODEL + h * HD + tid;
        g_AOhi[oi] = hv;
        g_AOlo[oi] = __float2half(v - __half2float(hv));
        __syncthreads();
    }
}

// ======================= launch (deep fork-join inside capture) =======================
extern "C" void kernel_launch(void* const* d_in, const int* in_sizes, int n_in,
                              void* d_out, int out_size)
{
    const float* X  = (const float*)d_in[0];
    const float* Wq = (const float*)d_in[2];
    const float* Wk = (const float*)d_in[3];
    const float* Wv = (const float*)d_in[4];
    const float* Wo = (const float*)d_in[5];
    float* out = (float*)d_out;

    static cudaStream_t s_aux = 0, s2 = 0;
    static cudaEvent_t ev_begin = 0, ev_xcvt = 0, ev_vdone = 0,
                       ev_rope = 0, ev_g0 = 0, ev_g1 = 0, ev_pvb = 0;
    if (!s_aux) {
        int lo_p, hi_p;
        cudaDeviceGetStreamPriorityRange(&lo_p, &hi_p);
        cudaStreamCreateWithPriority(&s_aux, cudaStreamNonBlocking, lo_p);
        cudaStreamCreateWithFlags(&s2, cudaStreamNonBlocking);
        cudaEventCreateWithFlags(&ev_begin, cudaEventDisableTiming);
        cudaEventCreateWithFlags(&ev_xcvt,  cudaEventDisableTiming);
        cudaEventCreateWithFlags(&ev_vdone, cudaEventDisableTiming);
        cudaEventCreateWithFlags(&ev_rope,  cudaEventDisableTiming);
        cudaEventCreateWithFlags(&ev_g0,    cudaEventDisableTiming);
        cudaEventCreateWithFlags(&ev_g1,    cudaEventDisableTiming);
        cudaEventCreateWithFlags(&ev_pvb,   cudaEventDisableTiming);
    }

    cudaFuncSetAttribute(mm_qkproj_kernel, cudaFuncAttributeMaxDynamicSharedMemorySize, MM_SMEM);
    cudaFuncSetAttribute(mm_v_kernel,      cudaFuncAttributeMaxDynamicSharedMemorySize, MM_SMEM);
    cudaFuncSetAttribute(mm_qk_kernel,     cudaFuncAttributeMaxDynamicSharedMemorySize, MM_SMEM);
    cudaFuncSetAttribute(mm_o_kernel,      cudaFuncAttributeMaxDynamicSharedMemorySize, MM_SMEM);

    // fork
    cudaEventRecord(ev_begin, 0);
    cudaStreamWaitEvent(s_aux, ev_begin, 0);
    cudaStreamWaitEvent(s2, ev_begin, 0);

    // aux: deferred weight conversions + V projection
    cvt_aux_kernel<<<(2 * W4 + 255) / 256, 256, 0, s_aux>>>(Wv, Wo);

    // main: X/Wq/Wk conversion, Q/K projections, rope
    cvt_main_kernel<<<(X4 + 2 * W4 + 255) / 256, 256>>>(X, Wq, Wk);
    cudaEventRecord(ev_xcvt, 0);

    mm_qkproj_kernel<<<dim3(DMODEL / 64, SEQ / 128, 2), 256, MM_SMEM>>>();
    rope_kernel<<<dim3((SEQ * NH * 64) / 256, 2), 256>>>();
    cudaEventRecord(ev_rope, 0);

    // aux: V projection once X is converted
    cudaStreamWaitEvent(s_aux, ev_xcvt, 0);
    mm_v_kernel<<<dim3(DMODEL / 64, SEQ / 128), 256, MM_SMEM, s_aux>>>();
    cudaEventRecord(ev_vdone, s_aux);

    // head-group 0 on default: qk -> softmax -> scan
    mm_qk_kernel<<<dim3(SEQ / 64, SEQ / 128, NH / 2), 256, MM_SMEM>>>(0);
    softmax_kernel<<<dim3(SEQ, NH / 2), 256>>>(0);
    scan_kernel<<<NH / 2, 128>>>(0);
    cudaEventRecord(ev_g0, 0);

    // head-group 1 on s2
    cudaStreamWaitEvent(s2, ev_rope, 0);
    mm_qk_kernel<<<dim3(SEQ / 64, SEQ / 128, NH / 2), 256, MM_SMEM, s2>>>(NH / 2);
    softmax_kernel<<<dim3(SEQ, NH / 2), 256, 0, s2>>>(NH / 2);
    scan_kernel<<<NH / 2, 128, 0, s2>>>(NH / 2);
    cudaEventRecord(ev_g1, s2);

    // pv halves: rows 0-511 on default, rows 512-1023 on s2
    cudaStreamWaitEvent(0, ev_g1, 0);
    cudaStreamWaitEvent(0, ev_vdone, 0);
    cudaStreamWaitEvent(s2, ev_g0, 0);
    cudaStreamWaitEvent(s2, ev_vdone, 0);

    pv_kernel<<<dim3(SEQ / 16, NH), 128>>>(0);
    pv_kernel<<<dim3(SEQ / 16, NH), 128, 0, s2>>>(SEQ / 16);
    cudaEventRecord(ev_pvb, s2);

    // mm_o halves: first half overlaps second pv half
    mm_o_kernel<<<dim3(DMODEL / 64, SEQ / 256), 256, MM_SMEM>>>(out, 0);
    cudaStreamWaitEvent(0, ev_pvb, 0);
    mm_o_kernel<<<dim3(DMODEL / 64, SEQ / 256), 256, MM_SMEM>>>(out, SEQ / 256);
}